// round 14
// baseline (speedup 1.0000x reference)
#include <cuda_runtime.h>
#include <cuda_fp16.h>
#include <cstdint>

#define S_LEN 2048
#define B_SZ  4
#define H_NUM 8
#define DKH   128
#define DM    1024

// Scratch (device globals — no allocations allowed)
__device__ __half g_Q[(size_t)B_SZ * H_NUM * S_LEN * DKH];  // [B,H,S,dk] fp16
__device__ __half g_K[(size_t)B_SZ * H_NUM * S_LEN * DKH];
__device__ __half g_V[(size_t)B_SZ * H_NUM * S_LEN * DKH];
__device__ float  g_O[(size_t)B_SZ * S_LEN * DM];           // [B,S,D] fp32
__device__ __half g_WqT[DM * DM];                           // W^T fp16: [n][k]
__device__ __half g_WkT[DM * DM];
__device__ __half g_WvT[DM * DM];
__device__ __half g_qh[(size_t)B_SZ * S_LEN * DM];          // fp16 copies of inputs
__device__ __half g_kh[(size_t)B_SZ * S_LEN * DM];
__device__ __half g_vh[(size_t)B_SZ * S_LEN * DM];

// ---------------------------------------------------------------------------
// helpers
// ---------------------------------------------------------------------------
__device__ __forceinline__ uint32_t pack2(float lo, float hi) {
    __half2 h = __float22half2_rn(make_float2(lo, hi));
    return *reinterpret_cast<uint32_t*>(&h);
}
__device__ __forceinline__ uint32_t smem_addr(const void* p) {
    return (uint32_t)__cvta_generic_to_shared(p);
}
__device__ __forceinline__ void cpa16(uint32_t dst, const void* src) {
    asm volatile("cp.async.cg.shared.global [%0], [%1], 16;" :: "r"(dst), "l"(src));
}
#define CP_COMMIT() asm volatile("cp.async.commit_group;" ::: "memory")
#define CP_WAIT(n)  asm volatile("cp.async.wait_group %0;" :: "n"(n) : "memory")

// D += A*B, m16n8k16 fp16 in / fp32 accum
__device__ __forceinline__ void mma16(float* d, const uint32_t* a, const uint32_t* b) {
    asm volatile(
        "mma.sync.aligned.m16n8k16.row.col.f32.f16.f16.f32 "
        "{%0,%1,%2,%3},{%4,%5,%6,%7},{%8,%9},{%0,%1,%2,%3};"
        : "+f"(d[0]), "+f"(d[1]), "+f"(d[2]), "+f"(d[3])
        : "r"(a[0]), "r"(a[1]), "r"(a[2]), "r"(a[3]), "r"(b[0]), "r"(b[1]));
}
#define LDSM4(r, addr)                                                        \
    asm volatile("ldmatrix.sync.aligned.m8n8.x4.shared.b16 {%0,%1,%2,%3},[%4];" \
        : "=r"((r)[0]), "=r"((r)[1]), "=r"((r)[2]), "=r"((r)[3]) : "r"(addr))
#define LDSM4T(r, addr)                                                       \
    asm volatile("ldmatrix.sync.aligned.m8n8.x4.trans.shared.b16 {%0,%1,%2,%3},[%4];" \
        : "=r"((r)[0]), "=r"((r)[1]), "=r"((r)[2]), "=r"((r)[3]) : "r"(addr))

// ---------------------------------------------------------------------------
// Fused preprocessing (single launch):
//   z in 0..2 : fp32 -> fp16 convert of inputs q/k/v
//   z in 3..5 : fp32 -> fp16 transpose of weights Wq/Wk/Wv
// ---------------------------------------------------------------------------
__global__ __launch_bounds__(256)
void prep(const float4* __restrict__ q4, const float4* __restrict__ k4,
          const float4* __restrict__ v4, uint2* __restrict__ qh,
          uint2* __restrict__ kh, uint2* __restrict__ vh,
          const float* __restrict__ Wq, const float* __restrict__ Wk,
          const float* __restrict__ Wv, __half* __restrict__ WqT,
          __half* __restrict__ WkT, __half* __restrict__ WvT)
{
    const int z = blockIdx.z;
    if (z < 3) {
        const float4* in = (z == 0) ? q4 : (z == 1) ? k4 : v4;
        uint2*       out = (z == 0) ? qh : (z == 1) ? kh : vh;
        size_t i = (size_t)blockIdx.x * 256 + threadIdx.x;
        float4 v = in[i];
        uint2 u;
        u.x = pack2(v.x, v.y);
        u.y = pack2(v.z, v.w);
        out[i] = u;
    } else {
        if (blockIdx.x >= 1024) return;
        const float* in  = (z == 3) ? Wq : (z == 4) ? Wk : Wv;
        __half*      out = (z == 3) ? WqT : (z == 4) ? WkT : WvT;
        const int bx = blockIdx.x & 31, by = blockIdx.x >> 5;
        const int tx = threadIdx.x & 31, ty = threadIdx.x >> 5;

        __shared__ float t[32][33];
        int x  = bx * 32 + tx;
        int y0 = by * 32;
#pragma unroll
        for (int j = ty; j < 32; j += 8)
            t[j][tx] = in[(size_t)(y0 + j) * DM + x];
        __syncthreads();
        int x2 = by * 32 + tx;
#pragma unroll
        for (int j = ty; j < 32; j += 8)
            out[(size_t)(bx * 32 + j) * DM + x2] = __float2half(t[tx][j]);
    }
}

// ---------------------------------------------------------------------------
// Fused fp16 mma GEMM (3 projections via blockIdx.z), 4-stage cp.async
// pipeline, single barrier per iter. Y = Xh @ W + b. M=8192 N=1024 K=1024.
// CTA 128x128, BK=32, 8 warps. smem row stride 40 halves: conflict-free.
// ---------------------------------------------------------------------------
#define GROWB  80                         // bytes per smem row
#define AMAT_B (128 * GROWB)              // 10240 bytes per matrix
#define STAGE_B (2 * AMAT_B)              // 20480 per stage
#define GEMM_SMEM (4 * STAGE_B)           // 81920 bytes

__global__ __launch_bounds__(256)
void gemm_h3(const __half* __restrict__ X0, const __half* __restrict__ X1,
             const __half* __restrict__ X2, const __half* __restrict__ W0,
             const __half* __restrict__ W1, const __half* __restrict__ W2,
             const float* __restrict__ b0, const float* __restrict__ b1,
             const float* __restrict__ b2, __half* __restrict__ o0,
             __half* __restrict__ o1, __half* __restrict__ o2)
{
    const int z = blockIdx.z;
    const __half* Xh   = (z == 0) ? X0 : (z == 1) ? X1 : X2;
    const __half* Wt   = (z == 0) ? W0 : (z == 1) ? W1 : W2;
    const float*  bias = (z == 0) ? b0 : (z == 1) ? b1 : b2;
    __half*       out  = (z == 0) ? o0 : (z == 1) ? o1 : o2;

    extern __shared__ __align__(16) char sm_raw[];
    const uint32_t sb = smem_addr(sm_raw);
    const int tid  = threadIdx.x;
    const int wid  = tid >> 5, lane = tid & 31;
    const int grp  = lane >> 2, kq = lane & 3;
    const int wm   = (wid >> 2) * 64, wn = (wid & 3) * 32;
    const int n0   = blockIdx.x * 128;   // h = blockIdx.x
    const int m0   = blockIdx.y * 128;

    float acc[4][4][4];
#pragma unroll
    for (int mt = 0; mt < 4; ++mt)
#pragma unroll
        for (int nt = 0; nt < 4; ++nt)
#pragma unroll
            for (int e = 0; e < 4; ++e) acc[mt][nt][e] = 0.0f;

    // cp.async tile loader: 512 16B chunks per matrix, 2 per thread
    auto load_stage = [&](int st, int kt) {
        const uint32_t base = sb + st * STAGE_B;
        const __half* Ag = Xh + (size_t)m0 * 1024 + kt * 32;
        const __half* Bg = Wt + (size_t)n0 * 1024 + kt * 32;
#pragma unroll
        for (int t = 0; t < 2; ++t) {
            int idx = tid + t * 256;          // 0..511
            int r = idx >> 2, c = idx & 3;
            cpa16(base + r * GROWB + c * 16,          Ag + (size_t)r * 1024 + c * 8);
            cpa16(base + AMAT_B + r * GROWB + c * 16, Bg + (size_t)r * 1024 + c * 8);
        }
    };

    // ldmatrix per-lane addressing
    const int arow = wm + ((lane >> 3) & 1) * 8 + (lane & 7);
    const int acol = (lane >> 4) * 8;                  // halves
    const int brow = wn + ((lane >> 4) & 1) * 8 + (lane & 7);
    const int bcol = ((lane >> 3) & 1) * 8;

    load_stage(0, 0); CP_COMMIT();
    load_stage(1, 1); CP_COMMIT();
    load_stage(2, 2); CP_COMMIT();

    for (int i = 0; i < 32; ++i) {
        CP_WAIT(2);
        __syncthreads();

        // refill stage freed last iteration ((i+3)&3 == (i-1)&3)
        if (i + 3 < 32) load_stage((i + 3) & 3, i + 3);
        CP_COMMIT();   // always commit to keep group accounting uniform

        const uint32_t Ac = sb + (i & 3) * STAGE_B;
        const uint32_t Bc = Ac + AMAT_B;
#pragma unroll
        for (int ks = 0; ks < 2; ++ks) {
            uint32_t a[4][4], b[2][4];
#pragma unroll
            for (int mt = 0; mt < 4; ++mt)
                LDSM4(a[mt], Ac + (arow + mt * 16) * GROWB + (ks * 16 + acol) * 2);
#pragma unroll
            for (int ntp = 0; ntp < 2; ++ntp)
                LDSM4(b[ntp], Bc + (brow + ntp * 16) * GROWB + (ks * 16 + bcol) * 2);
#pragma unroll
            for (int mt = 0; mt < 4; ++mt) {
                mma16(acc[mt][0], a[mt], &b[0][0]);
                mma16(acc[mt][1], a[mt], &b[0][2]);
                mma16(acc[mt][2], a[mt], &b[1][0]);
                mma16(acc[mt][3], a[mt], &b[1][2]);
            }
        }
    }

    // epilogue: bias + fp16 head-split store ([B,H,S,dk])
    const int h = blockIdx.x;
#pragma unroll
    for (int mt = 0; mt < 4; ++mt) {
#pragma unroll
        for (int half_ = 0; half_ < 2; ++half_) {
            int m = m0 + wm + mt * 16 + grp + half_ * 8;
            int b = m >> 11, s = m & 2047;
            __half* orow = out + (((size_t)b * H_NUM + h) * S_LEN + s) * DKH;
#pragma unroll
            for (int nt = 0; nt < 4; ++nt) {
                int nl = wn + nt * 8 + 2 * kq;
                float2 bv = *reinterpret_cast<const float2*>(bias + n0 + nl);
                uint32_t u = pack2(acc[mt][nt][half_ * 2 + 0] + bv.x,
                                   acc[mt][nt][half_ * 2 + 1] + bv.y);
                *reinterpret_cast<uint32_t*>(orow + nl) = u;
            }
        }
    }
}

// ---------------------------------------------------------------------------
// Flash attention, fp16 mma, BQ=128 (8 warps), BKV=64, dk=128.
// Double-buffered K/V cp.async; 2 CTAs/SM (launch_bounds minBlocks=2).
// ---------------------------------------------------------------------------
#define KST2 136
#define VST2 136
#define PST2 72
#define KV_K_B  (64 * KST2 * 2)              // 17408 bytes (K region)
#define KV_ST_B (2 * KV_K_B)                 // 34816 bytes per stage (K+V)
#define ATT_P_OFF (2 * KV_ST_B)              // 69632
#define ATT_SMEM (ATT_P_OFF + 8 * 16 * PST2 * 2)  // 88064 bytes

__global__ __launch_bounds__(256, 2)
void attn_h(const __half* __restrict__ Q, const __half* __restrict__ K,
            const __half* __restrict__ V, float* __restrict__ O)
{
    extern __shared__ __align__(16) char sm_raw[];
    const uint32_t sb = smem_addr(sm_raw);
    __half* Ps = reinterpret_cast<__half*>(sm_raw + ATT_P_OFF);

    const int qt  = (int)gridDim.x - 1 - (int)blockIdx.x;  // heavy tiles first
    const int bh  = blockIdx.y;
    const int tid = threadIdx.x;
    const int w   = tid >> 5, lane = tid & 31;
    const int grp = lane >> 2, kq = lane & 3;
    const int nkv = 2 * qt + 2;              // kv tiles (BKV=64) for BQ=128

    const __half* Qg = Q + ((size_t)bh * S_LEN + (size_t)qt * 128) * DKH;
    const __half* Kg = K + (size_t)bh * S_LEN * DKH;
    const __half* Vg = V + (size_t)bh * S_LEN * DKH;

    // kv tile loader into stage st (K + V), 1024 chunks over 256 threads
    auto load_kv = [&](int st, int kt) {
        const uint32_t kb = sb + st * KV_ST_B;
        const uint32_t vb = kb + KV_K_B;
        const __half* Kt = Kg + (size_t)kt * 64 * DKH;
        const __half* Vt = Vg + (size_t)kt * 64 * DKH;
#pragma unroll
        for (int j = 0; j < 4; ++j) {
            int idx = tid + j * 256;
            int r = idx >> 4, c = idx & 15;
            cpa16(kb + r * (KST2 * 2) + c * 16, Kt + (size_t)r * DKH + c * 8);
            cpa16(vb + r * (VST2 * 2) + c * 16, Vt + (size_t)r * DKH + c * 8);
        }
    };

    // ---- stage Q (128 rows x 128 cols = 2048 chunks) into stage-1 K+V
    // regions (contiguous: row r at qb + r*272 for r in 0..127), plus kv0 ----
    {
        const uint32_t qb = sb + KV_ST_B;   // stage 1 base
#pragma unroll
        for (int j = 0; j < 8; ++j) {
            int idx = tid + j * 256;
            int r = idx >> 4, c = idx & 15;
            cpa16(qb + r * (KST2 * 2) + c * 16, Qg + (size_t)r * DKH + c * 8);
        }
        CP_COMMIT();
        load_kv(0, 0);
        CP_COMMIT();
    }
    CP_WAIT(1);        // Q ready (kv0 may still be in flight)
    __syncthreads();

    // ---- extract Q A-fragments (warp w owns rows w*16..w*16+15) ----
    uint32_t qa[8][4];
    {
        const int qrow = w * 16 + ((lane >> 3) & 1) * 8 + (lane & 7);
        const int qcol = (lane >> 4) * 8;
        const uint32_t qb = sb + KV_ST_B;
#pragma unroll
        for (int ks = 0; ks < 8; ++ks)
            LDSM4(qa[ks], qb + (qrow * KST2 + ks * 16 + qcol) * 2);
    }

    float o[16][4];
#pragma unroll
    for (int nt = 0; nt < 16; ++nt)
#pragma unroll
        for (int e = 0; e < 4; ++e) o[nt][e] = 0.0f;
    float m0 = -1e30f, m1 = -1e30f, l0 = 0.0f, l1 = 0.0f;

    const float sc = 0.08838834764831843f;  // 1/sqrt(128)
    const int rowlo = w * 16 + grp;          // tile-local Q row (0..127)
    const int rowhi = rowlo + 8;

    // ldmatrix lane addressing (per iter)
    const int krow_l = ((lane >> 4) & 1) * 8 + (lane & 7);   // K B-frag rows
    const int kcol_l = ((lane >> 3) & 1) * 8;
    const int prow_l = ((lane >> 3) & 1) * 8 + (lane & 7);   // P A-frag rows
    const int pcol_l = (lane >> 4) * 8;
    const int lrow   = ((lane >> 3) & 1) * 8 + (lane & 7);   // V trans rows
    const int lcol   = (lane >> 4) * 8;

    for (int kt = 0; kt < nkv; ++kt) {
        CP_WAIT(0);        // kv tile kt resident
        __syncthreads();   // all warps past last iter's compute + this wait

        // prefetch next kv tile into the other stage (overwrites oldest/Q)
        if (kt + 1 < nkv) load_kv((kt + 1) & 1, kt + 1);
        CP_COMMIT();       // always commit (uniform group accounting)

        const uint32_t Kst = sb + (kt & 1) * KV_ST_B;
        const uint32_t Vst = Kst + KV_K_B;

        // ---- S = Q @ K^T : 8 k16-steps x 4 nt-pairs (ldmatrix.x4) ----
        float sfr[8][4];
#pragma unroll
        for (int nt = 0; nt < 8; ++nt)
#pragma unroll
            for (int e = 0; e < 4; ++e) sfr[nt][e] = 0.0f;

#pragma unroll
        for (int ks = 0; ks < 8; ++ks) {
#pragma unroll
            for (int ntp = 0; ntp < 4; ++ntp) {
                uint32_t bb[4];
                LDSM4(bb, Kst + ((ntp * 16 + krow_l) * KST2 + ks * 16 + kcol_l) * 2);
                mma16(sfr[2 * ntp + 0], qa[ks], &bb[0]);
                mma16(sfr[2 * ntp + 1], qa[ks], &bb[2]);
            }
        }

        // scale + causal mask (kv cols kt*64.. vs Q rows qt*128..):
        // mask applies when kt >= 2*qt; col offset within Q tile = (kt-2qt)*64
#pragma unroll
        for (int nt = 0; nt < 8; ++nt) {
#pragma unroll
            for (int e = 0; e < 4; ++e) sfr[nt][e] *= sc;
            if (kt >= 2 * qt) {
                int col = (kt - 2 * qt) * 64 + nt * 8 + 2 * kq;
                if (col + 0 > rowlo) sfr[nt][0] = -1e9f;
                if (col + 1 > rowlo) sfr[nt][1] = -1e9f;
                if (col + 0 > rowhi) sfr[nt][2] = -1e9f;
                if (col + 1 > rowhi) sfr[nt][3] = -1e9f;
            }
        }

        // ---- online softmax ----
        float mx0 = -1e30f, mx1 = -1e30f;
#pragma unroll
        for (int nt = 0; nt < 8; ++nt) {
            mx0 = fmaxf(mx0, fmaxf(sfr[nt][0], sfr[nt][1]));
            mx1 = fmaxf(mx1, fmaxf(sfr[nt][2], sfr[nt][3]));
        }
        mx0 = fmaxf(mx0, __shfl_xor_sync(0xffffffffu, mx0, 1));
        mx0 = fmaxf(mx0, __shfl_xor_sync(0xffffffffu, mx0, 2));
        mx1 = fmaxf(mx1, __shfl_xor_sync(0xffffffffu, mx1, 1));
        mx1 = fmaxf(mx1, __shfl_xor_sync(0xffffffffu, mx1, 2));

        float mn0 = fmaxf(m0, mx0), mn1 = fmaxf(m1, mx1);
        float c0 = __expf(m0 - mn0), c1 = __expf(m1 - mn1);
        m0 = mn0; m1 = mn1;

        float s0 = 0.0f, s1 = 0.0f;
#pragma unroll
        for (int nt = 0; nt < 8; ++nt) {
            sfr[nt][0] = __expf(sfr[nt][0] - m0);
            sfr[nt][1] = __expf(sfr[nt][1] - m0);
            sfr[nt][2] = __expf(sfr[nt][2] - m1);
            sfr[nt][3] = __expf(sfr[nt][3] - m1);
            s0 += sfr[nt][0] + sfr[nt][1];
            s1 += sfr[nt][2] + sfr[nt][3];
        }
        s0 += __shfl_xor_sync(0xffffffffu, s0, 1);
        s0 += __shfl_xor_sync(0xffffffffu, s0, 2);
        s1 += __shfl_xor_sync(0xffffffffu, s1, 1);
        s1 += __shfl_xor_sync(0xffffffffu, s1, 2);
        l0 = l0 * c0 + s0;
        l1 = l1 * c1 + s1;

#pragma unroll
        for (int nt = 0; nt < 16; ++nt) {
            o[nt][0] *= c0; o[nt][1] *= c0;
            o[nt][2] *= c1; o[nt][3] *= c1;
        }

        // ---- P (fp16) to warp-private smem ----
        __half* Pw = Ps + w * (16 * PST2);
        const uint32_t Pwb = smem_addr(Pw);
#pragma unroll
        for (int nt = 0; nt < 8; ++nt) {
            int col = nt * 8 + 2 * kq;
            *reinterpret_cast<uint32_t*>(Pw + grp * PST2 + col) =
                pack2(sfr[nt][0], sfr[nt][1]);
            *reinterpret_cast<uint32_t*>(Pw + (grp + 8) * PST2 + col) =
                pack2(sfr[nt][2], sfr[nt][3]);
        }
        __syncwarp();

        // ---- O += P @ V : 4 k16-steps; P via ldmatrix, V via ldmatrix.trans ----
#pragma unroll
        for (int ks = 0; ks < 4; ++ks) {
            uint32_t a[4];
            LDSM4(a, Pwb + (prow_l * PST2 + ks * 16 + pcol_l) * 2);
            const uint32_t vbase = Vst + ((ks * 16 + lrow) * VST2 + lcol) * 2;
#pragma unroll
            for (int ntp = 0; ntp < 8; ++ntp) {
                uint32_t bb[4];
                LDSM4T(bb, vbase + ntp * 32);
                mma16(o[2 * ntp + 0], a, &bb[0]);
                mma16(o[2 * ntp + 1], a, &bb[2]);
            }
        }
        __syncwarp();
    }

    // ---- epilogue: normalize, write fp32 [B,S,D] ----
    const int b = bh >> 3, h = bh & 7;
    float i0 = 1.0f / l0, i1 = 1.0f / l1;
    int q0 = qt * 128 + rowlo;
    float* r0 = O + ((size_t)b * S_LEN + q0) * DM + h * DKH;
    float* r1 = O + ((size_t)b * S_LEN + q0 + 8) * DM + h * DKH;
#pragma unroll
    for (int nt = 0; nt < 16; ++nt) {
        int col = nt * 8 + 2 * kq;
        *reinterpret_cast<float2*>(r0 + col) = make_float2(o[nt][0] * i0, o[nt][1] * i0);
        *reinterpret_cast<float2*>(r1 + col) = make_float2(o[nt][2] * i1, o[nt][3] * i1);
    }
}

// ---------------------------------------------------------------------------
// Residual + LayerNorm
// ---------------------------------------------------------------------------
__global__ __launch_bounds__(256)
void ln_kernel(const float* __restrict__ Oin, const float* __restrict__ X,
               const float* __restrict__ gamma, const float* __restrict__ beta,
               float* __restrict__ out)
{
    const int r = blockIdx.x;
    const int t = threadIdx.x;

    float4 o = reinterpret_cast<const float4*>(Oin + (size_t)r * DM)[t];
    float4 x = reinterpret_cast<const float4*>(X + (size_t)r * DM)[t];
    float v0 = o.x + x.x, v1 = o.y + x.y, v2 = o.z + x.z, v3 = o.w + x.w;

    float s1 = v0 + v1 + v2 + v3;
    float s2 = v0 * v0 + v1 * v1 + v2 * v2 + v3 * v3;
#pragma unroll
    for (int off = 16; off > 0; off >>= 1) {
        s1 += __shfl_xor_sync(0xffffffffu, s1, off);
        s2 += __shfl_xor_sync(0xffffffffu, s2, off);
    }

    __shared__ float rs1[8], rs2[8], stats[2];
    int warp = t >> 5, lane = t & 31;
    if (lane == 0) { rs1[warp] = s1; rs2[warp] = s2; }
    __syncthreads();
    if (t == 0) {
        float a = 0.0f, b2 = 0.0f;
#pragma unroll
        for (int wdx = 0; wdx < 8; ++wdx) { a += rs1[wdx]; b2 += rs2[wdx]; }
        float mean = a * (1.0f / 1024.0f);
        float var  = b2 * (1.0f / 1024.0f) - mean * mean;
        stats[0] = mean;
        stats[1] = rsqrtf(var + 1e-6f);
    }
    __syncthreads();
    float mean = stats[0], rstd = stats[1];

    float4 g  = reinterpret_cast<const float4*>(gamma)[t];
    float4 bb = reinterpret_cast<const float4*>(beta)[t];
    float4 y;
    y.x = (v0 - mean) * rstd * g.x + bb.x;
    y.y = (v1 - mean) * rstd * g.y + bb.y;
    y.z = (v2 - mean) * rstd * g.z + bb.z;
    y.w = (v3 - mean) * rstd * g.w + bb.w;
    reinterpret_cast<float4*>(out + (size_t)r * DM)[t] = y;
}

// ---------------------------------------------------------------------------
// Launcher
// ---------------------------------------------------------------------------
extern "C" void kernel_launch(void* const* d_in, const int* in_sizes, int n_in,
                              void* d_out, int out_size)
{
    const float* q     = (const float*)d_in[0];
    const float* k     = (const float*)d_in[1];
    const float* v     = (const float*)d_in[2];
    const float* Wq    = (const float*)d_in[3];
    const float* bq    = (const float*)d_in[4];
    const float* Wk    = (const float*)d_in[5];
    const float* bk    = (const float*)d_in[6];
    const float* Wv    = (const float*)d_in[7];
    const float* bv    = (const float*)d_in[8];
    const float* gamma = (const float*)d_in[9];
    const float* beta  = (const float*)d_in[10];
    float* out = (float*)d_out;

    __half *Qp, *Kp, *Vp, *WqT, *WkT, *WvT, *qh, *kh, *vh;
    float *Op;
    cudaGetSymbolAddress((void**)&Qp, g_Q);
    cudaGetSymbolAddress((void**)&Kp, g_K);
    cudaGetSymbolAddress((void**)&Vp, g_V);
    cudaGetSymbolAddress((void**)&Op, g_O);
    cudaGetSymbolAddress((void**)&WqT, g_WqT);
    cudaGetSymbolAddress((void**)&WkT, g_WkT);
    cudaGetSymbolAddress((void**)&WvT, g_WvT);
    cudaGetSymbolAddress((void**)&qh, g_qh);
    cudaGetSymbolAddress((void**)&kh, g_kh);
    cudaGetSymbolAddress((void**)&vh, g_vh);

    cudaFuncSetAttribute(gemm_h3, cudaFuncAttributeMaxDynamicSharedMemorySize,
                         GEMM_SMEM);
    cudaFuncSetAttribute(attn_h, cudaFuncAttributeMaxDynamicSharedMemorySize,
                         ATT_SMEM);

    // launch 0: all preprocessing (f2h x3 + weight transpose x3)
    prep<<<dim3(8192, 1, 6), 256>>>((const float4*)q, (const float4*)k,
                                    (const float4*)v, (uint2*)qh, (uint2*)kh,
                                    (uint2*)vh, Wq, Wk, Wv, WqT, WkT, WvT);

    // launch 1: fused QKV projections
    gemm_h3<<<dim3(8, 64, 3), 256, GEMM_SMEM>>>(qh, kh, vh, WqT, WkT, WvT,
                                                bq, bk, bv, Qp, Kp, Vp);

    // launch 2: attention (2 CTAs/SM)
    attn_h<<<dim3(16, 32), 256, ATT_SMEM>>>(Qp, Kp, Vp, Op);

    // launch 3: residual + layernorm
    ln_kernel<<<8192, 256>>>(Op, q, gamma, beta, out);
}

// round 15
// speedup vs baseline: 1.1299x; 1.1299x over previous
#include <cuda_runtime.h>
#include <cuda_fp16.h>
#include <cstdint>

#define S_LEN 2048
#define B_SZ  4
#define H_NUM 8
#define DKH   128
#define DM    1024

// Scratch (device globals — no allocations allowed)
__device__ __half g_Q[(size_t)B_SZ * H_NUM * S_LEN * DKH];  // [B,H,S,dk] fp16
__device__ __half g_K[(size_t)B_SZ * H_NUM * S_LEN * DKH];
__device__ __half g_V[(size_t)B_SZ * H_NUM * S_LEN * DKH];
__device__ float  g_O[(size_t)B_SZ * S_LEN * DM];           // [B,S,D] fp32
__device__ __half g_WqT[DM * DM];                           // W^T fp16: [n][k]
__device__ __half g_WkT[DM * DM];
__device__ __half g_WvT[DM * DM];
__device__ __half g_qh[(size_t)B_SZ * S_LEN * DM];          // fp16 copies of inputs
__device__ __half g_kh[(size_t)B_SZ * S_LEN * DM];
__device__ __half g_vh[(size_t)B_SZ * S_LEN * DM];

// ---------------------------------------------------------------------------
// helpers
// ---------------------------------------------------------------------------
__device__ __forceinline__ uint32_t pack2(float lo, float hi) {
    __half2 h = __float22half2_rn(make_float2(lo, hi));
    return *reinterpret_cast<uint32_t*>(&h);
}
__device__ __forceinline__ uint32_t smem_addr(const void* p) {
    return (uint32_t)__cvta_generic_to_shared(p);
}
__device__ __forceinline__ void cpa16(uint32_t dst, const void* src) {
    asm volatile("cp.async.cg.shared.global [%0], [%1], 16;" :: "r"(dst), "l"(src));
}
#define CP_COMMIT() asm volatile("cp.async.commit_group;" ::: "memory")
#define CP_WAIT(n)  asm volatile("cp.async.wait_group %0;" :: "n"(n) : "memory")

// D += A*B, m16n8k16 fp16 in / fp32 accum
__device__ __forceinline__ void mma16(float* d, const uint32_t* a, const uint32_t* b) {
    asm volatile(
        "mma.sync.aligned.m16n8k16.row.col.f32.f16.f16.f32 "
        "{%0,%1,%2,%3},{%4,%5,%6,%7},{%8,%9},{%0,%1,%2,%3};"
        : "+f"(d[0]), "+f"(d[1]), "+f"(d[2]), "+f"(d[3])
        : "r"(a[0]), "r"(a[1]), "r"(a[2]), "r"(a[3]), "r"(b[0]), "r"(b[1]));
}
#define LDSM4(r, addr)                                                        \
    asm volatile("ldmatrix.sync.aligned.m8n8.x4.shared.b16 {%0,%1,%2,%3},[%4];" \
        : "=r"((r)[0]), "=r"((r)[1]), "=r"((r)[2]), "=r"((r)[3]) : "r"(addr))
#define LDSM4T(r, addr)                                                       \
    asm volatile("ldmatrix.sync.aligned.m8n8.x4.trans.shared.b16 {%0,%1,%2,%3},[%4];" \
        : "=r"((r)[0]), "=r"((r)[1]), "=r"((r)[2]), "=r"((r)[3]) : "r"(addr))

// ---------------------------------------------------------------------------
// Fused preprocessing (single launch):
//   z in 0..2 : fp32 -> fp16 convert of inputs q/k/v
//   z in 3..5 : fp32 -> fp16 transpose of weights Wq/Wk/Wv
// ---------------------------------------------------------------------------
__global__ __launch_bounds__(256)
void prep(const float4* __restrict__ q4, const float4* __restrict__ k4,
          const float4* __restrict__ v4, uint2* __restrict__ qh,
          uint2* __restrict__ kh, uint2* __restrict__ vh,
          const float* __restrict__ Wq, const float* __restrict__ Wk,
          const float* __restrict__ Wv, __half* __restrict__ WqT,
          __half* __restrict__ WkT, __half* __restrict__ WvT)
{
    const int z = blockIdx.z;
    if (z < 3) {
        const float4* in = (z == 0) ? q4 : (z == 1) ? k4 : v4;
        uint2*       out = (z == 0) ? qh : (z == 1) ? kh : vh;
        size_t i = (size_t)blockIdx.x * 256 + threadIdx.x;
        float4 v = in[i];
        uint2 u;
        u.x = pack2(v.x, v.y);
        u.y = pack2(v.z, v.w);
        out[i] = u;
    } else {
        if (blockIdx.x >= 1024) return;
        const float* in  = (z == 3) ? Wq : (z == 4) ? Wk : Wv;
        __half*      out = (z == 3) ? WqT : (z == 4) ? WkT : WvT;
        const int bx = blockIdx.x & 31, by = blockIdx.x >> 5;
        const int tx = threadIdx.x & 31, ty = threadIdx.x >> 5;

        __shared__ float t[32][33];
        int x  = bx * 32 + tx;
        int y0 = by * 32;
#pragma unroll
        for (int j = ty; j < 32; j += 8)
            t[j][tx] = in[(size_t)(y0 + j) * DM + x];
        __syncthreads();
        int x2 = by * 32 + tx;
#pragma unroll
        for (int j = ty; j < 32; j += 8)
            out[(size_t)(bx * 32 + j) * DM + x2] = __float2half(t[tx][j]);
    }
}

// ---------------------------------------------------------------------------
// Fused fp16 mma GEMM (3 projections via blockIdx.z), 4-stage cp.async
// pipeline, single barrier per iter. Y = Xh @ W + b. M=8192 N=1024 K=1024.
// CTA 128x128, BK=32, 8 warps. smem row stride 40 halves: conflict-free.
// ---------------------------------------------------------------------------
#define GROWB  80                         // bytes per smem row
#define AMAT_B (128 * GROWB)              // 10240 bytes per matrix
#define STAGE_B (2 * AMAT_B)              // 20480 per stage
#define GEMM_SMEM (4 * STAGE_B)           // 81920 bytes

__global__ __launch_bounds__(256)
void gemm_h3(const __half* __restrict__ X0, const __half* __restrict__ X1,
             const __half* __restrict__ X2, const __half* __restrict__ W0,
             const __half* __restrict__ W1, const __half* __restrict__ W2,
             const float* __restrict__ b0, const float* __restrict__ b1,
             const float* __restrict__ b2, __half* __restrict__ o0,
             __half* __restrict__ o1, __half* __restrict__ o2)
{
    const int z = blockIdx.z;
    const __half* Xh   = (z == 0) ? X0 : (z == 1) ? X1 : X2;
    const __half* Wt   = (z == 0) ? W0 : (z == 1) ? W1 : W2;
    const float*  bias = (z == 0) ? b0 : (z == 1) ? b1 : b2;
    __half*       out  = (z == 0) ? o0 : (z == 1) ? o1 : o2;

    extern __shared__ __align__(16) char sm_raw[];
    const uint32_t sb = smem_addr(sm_raw);
    const int tid  = threadIdx.x;
    const int wid  = tid >> 5, lane = tid & 31;
    const int grp  = lane >> 2, kq = lane & 3;
    const int wm   = (wid >> 2) * 64, wn = (wid & 3) * 32;
    const int n0   = blockIdx.x * 128;   // h = blockIdx.x
    const int m0   = blockIdx.y * 128;

    float acc[4][4][4];
#pragma unroll
    for (int mt = 0; mt < 4; ++mt)
#pragma unroll
        for (int nt = 0; nt < 4; ++nt)
#pragma unroll
            for (int e = 0; e < 4; ++e) acc[mt][nt][e] = 0.0f;

    // cp.async tile loader: 512 16B chunks per matrix, 2 per thread
    auto load_stage = [&](int st, int kt) {
        const uint32_t base = sb + st * STAGE_B;
        const __half* Ag = Xh + (size_t)m0 * 1024 + kt * 32;
        const __half* Bg = Wt + (size_t)n0 * 1024 + kt * 32;
#pragma unroll
        for (int t = 0; t < 2; ++t) {
            int idx = tid + t * 256;          // 0..511
            int r = idx >> 2, c = idx & 3;
            cpa16(base + r * GROWB + c * 16,          Ag + (size_t)r * 1024 + c * 8);
            cpa16(base + AMAT_B + r * GROWB + c * 16, Bg + (size_t)r * 1024 + c * 8);
        }
    };

    // ldmatrix per-lane addressing
    const int arow = wm + ((lane >> 3) & 1) * 8 + (lane & 7);
    const int acol = (lane >> 4) * 8;                  // halves
    const int brow = wn + ((lane >> 4) & 1) * 8 + (lane & 7);
    const int bcol = ((lane >> 3) & 1) * 8;

    load_stage(0, 0); CP_COMMIT();
    load_stage(1, 1); CP_COMMIT();
    load_stage(2, 2); CP_COMMIT();

    for (int i = 0; i < 32; ++i) {
        CP_WAIT(2);
        __syncthreads();

        // refill stage freed last iteration ((i+3)&3 == (i-1)&3)
        if (i + 3 < 32) load_stage((i + 3) & 3, i + 3);
        CP_COMMIT();   // always commit to keep group accounting uniform

        const uint32_t Ac = sb + (i & 3) * STAGE_B;
        const uint32_t Bc = Ac + AMAT_B;
#pragma unroll
        for (int ks = 0; ks < 2; ++ks) {
            uint32_t a[4][4], b[2][4];
#pragma unroll
            for (int mt = 0; mt < 4; ++mt)
                LDSM4(a[mt], Ac + (arow + mt * 16) * GROWB + (ks * 16 + acol) * 2);
#pragma unroll
            for (int ntp = 0; ntp < 2; ++ntp)
                LDSM4(b[ntp], Bc + (brow + ntp * 16) * GROWB + (ks * 16 + bcol) * 2);
#pragma unroll
            for (int mt = 0; mt < 4; ++mt) {
                mma16(acc[mt][0], a[mt], &b[0][0]);
                mma16(acc[mt][1], a[mt], &b[0][2]);
                mma16(acc[mt][2], a[mt], &b[1][0]);
                mma16(acc[mt][3], a[mt], &b[1][2]);
            }
        }
    }

    // epilogue: bias + fp16 head-split store ([B,H,S,dk])
    const int h = blockIdx.x;
#pragma unroll
    for (int mt = 0; mt < 4; ++mt) {
#pragma unroll
        for (int half_ = 0; half_ < 2; ++half_) {
            int m = m0 + wm + mt * 16 + grp + half_ * 8;
            int b = m >> 11, s = m & 2047;
            __half* orow = out + (((size_t)b * H_NUM + h) * S_LEN + s) * DKH;
#pragma unroll
            for (int nt = 0; nt < 4; ++nt) {
                int nl = wn + nt * 8 + 2 * kq;
                float2 bv = *reinterpret_cast<const float2*>(bias + n0 + nl);
                uint32_t u = pack2(acc[mt][nt][half_ * 2 + 0] + bv.x,
                                   acc[mt][nt][half_ * 2 + 1] + bv.y);
                *reinterpret_cast<uint32_t*>(orow + nl) = u;
            }
        }
    }
}

// ---------------------------------------------------------------------------
// Flash attention, fp16 mma, BQ=64 (4 warps, 128 thr), BKV=64, dk=128.
// FA2 register identity: S C-fragments ARE the PV A-fragments — P never
// touches smem. 2-stage K/V cp.async pipeline. 3 CTAs/SM.
// ---------------------------------------------------------------------------
#define KST2 136
#define VST2 136
#define KV_K_B  (64 * KST2 * 2)              // 17408 bytes (K region)
#define KV_ST_B (2 * KV_K_B)                 // 34816 bytes per stage (K+V)
#define ATT_SMEM (2 * KV_ST_B)               // 69632 bytes

__global__ __launch_bounds__(128, 3)
void attn_h(const __half* __restrict__ Q, const __half* __restrict__ K,
            const __half* __restrict__ V, float* __restrict__ O)
{
    extern __shared__ __align__(16) char sm_raw[];
    const uint32_t sb = smem_addr(sm_raw);

    const int qt  = (int)gridDim.x - 1 - (int)blockIdx.x;  // heavy tiles first
    const int bh  = blockIdx.y;
    const int tid = threadIdx.x;
    const int w   = tid >> 5, lane = tid & 31;
    const int grp = lane >> 2, kq = lane & 3;

    const __half* Qg = Q + ((size_t)bh * S_LEN + (size_t)qt * 64) * DKH;
    const __half* Kg = K + (size_t)bh * S_LEN * DKH;
    const __half* Vg = V + (size_t)bh * S_LEN * DKH;

    // kv tile loader into stage st (K + V), 1024 chunks over 128 threads
    auto load_kv = [&](int st, int kt) {
        const uint32_t kb = sb + st * KV_ST_B;
        const uint32_t vb = kb + KV_K_B;
        const __half* Kt = Kg + (size_t)kt * 64 * DKH;
        const __half* Vt = Vg + (size_t)kt * 64 * DKH;
#pragma unroll
        for (int j = 0; j < 8; ++j) {
            int idx = tid + j * 128;
            int r = idx >> 4, c = idx & 15;
            cpa16(kb + r * (KST2 * 2) + c * 16, Kt + (size_t)r * DKH + c * 8);
            cpa16(vb + r * (VST2 * 2) + c * 16, Vt + (size_t)r * DKH + c * 8);
        }
    };

    // ---- stage Q (64 rows x 16 chunks = 1024) into stage-1 K region ----
    {
        const uint32_t qb = sb + KV_ST_B;   // stage 1 K region
#pragma unroll
        for (int j = 0; j < 8; ++j) {
            int idx = tid + j * 128;
            int r = idx >> 4, c = idx & 15;
            cpa16(qb + r * (KST2 * 2) + c * 16, Qg + (size_t)r * DKH + c * 8);
        }
        CP_COMMIT();
        load_kv(0, 0);
        CP_COMMIT();
    }
    CP_WAIT(1);        // Q ready (kv0 may still be in flight)
    __syncthreads();

    // ---- extract Q A-fragments ----
    uint32_t qa[8][4];
    {
        const int qrow = w * 16 + ((lane >> 3) & 1) * 8 + (lane & 7);
        const int qcol = (lane >> 4) * 8;
        const uint32_t qb = sb + KV_ST_B;
#pragma unroll
        for (int ks = 0; ks < 8; ++ks)
            LDSM4(qa[ks], qb + (qrow * KST2 + ks * 16 + qcol) * 2);
    }

    float o[16][4];
#pragma unroll
    for (int nt = 0; nt < 16; ++nt)
#pragma unroll
        for (int e = 0; e < 4; ++e) o[nt][e] = 0.0f;
    float m0 = -1e30f, m1 = -1e30f, l0 = 0.0f, l1 = 0.0f;

    const float sc = 0.08838834764831843f;  // 1/sqrt(128)
    const int rowlo = w * 16 + grp;
    const int rowhi = rowlo + 8;

    // ldmatrix lane addressing (per iter)
    const int krow_l = ((lane >> 4) & 1) * 8 + (lane & 7);   // K B-frag rows
    const int kcol_l = ((lane >> 3) & 1) * 8;
    const int lrow   = ((lane >> 3) & 1) * 8 + (lane & 7);   // V trans rows
    const int lcol   = (lane >> 4) * 8;

    for (int kt = 0; kt <= qt; ++kt) {
        CP_WAIT(0);        // kv tile kt resident
        __syncthreads();   // all warps past last iter's compute + this wait

        // prefetch next kv tile into the other stage (overwrites oldest/Q)
        if (kt + 1 <= qt) load_kv((kt + 1) & 1, kt + 1);
        CP_COMMIT();       // always commit (uniform group accounting)

        const uint32_t Kst = sb + (kt & 1) * KV_ST_B;
        const uint32_t Vst = Kst + KV_K_B;

        // ---- S = Q @ K^T : 8 k16-steps x 4 nt-pairs (ldmatrix.x4) ----
        float sfr[8][4];
#pragma unroll
        for (int nt = 0; nt < 8; ++nt)
#pragma unroll
            for (int e = 0; e < 4; ++e) sfr[nt][e] = 0.0f;

#pragma unroll
        for (int ks = 0; ks < 8; ++ks) {
#pragma unroll
            for (int ntp = 0; ntp < 4; ++ntp) {
                uint32_t bb[4];
                LDSM4(bb, Kst + ((ntp * 16 + krow_l) * KST2 + ks * 16 + kcol_l) * 2);
                mma16(sfr[2 * ntp + 0], qa[ks], &bb[0]);
                mma16(sfr[2 * ntp + 1], qa[ks], &bb[2]);
            }
        }

        // scale + causal mask on diagonal tile
#pragma unroll
        for (int nt = 0; nt < 8; ++nt) {
#pragma unroll
            for (int e = 0; e < 4; ++e) sfr[nt][e] *= sc;
            if (kt == qt) {
                int col = nt * 8 + 2 * kq;
                if (col + 0 > rowlo) sfr[nt][0] = -1e9f;
                if (col + 1 > rowlo) sfr[nt][1] = -1e9f;
                if (col + 0 > rowhi) sfr[nt][2] = -1e9f;
                if (col + 1 > rowhi) sfr[nt][3] = -1e9f;
            }
        }

        // ---- online softmax ----
        float mx0 = -1e30f, mx1 = -1e30f;
#pragma unroll
        for (int nt = 0; nt < 8; ++nt) {
            mx0 = fmaxf(mx0, fmaxf(sfr[nt][0], sfr[nt][1]));
            mx1 = fmaxf(mx1, fmaxf(sfr[nt][2], sfr[nt][3]));
        }
        mx0 = fmaxf(mx0, __shfl_xor_sync(0xffffffffu, mx0, 1));
        mx0 = fmaxf(mx0, __shfl_xor_sync(0xffffffffu, mx0, 2));
        mx1 = fmaxf(mx1, __shfl_xor_sync(0xffffffffu, mx1, 1));
        mx1 = fmaxf(mx1, __shfl_xor_sync(0xffffffffu, mx1, 2));

        float mn0 = fmaxf(m0, mx0), mn1 = fmaxf(m1, mx1);
        float c0 = __expf(m0 - mn0), c1 = __expf(m1 - mn1);
        m0 = mn0; m1 = mn1;

        float s0 = 0.0f, s1 = 0.0f;
#pragma unroll
        for (int nt = 0; nt < 8; ++nt) {
            sfr[nt][0] = __expf(sfr[nt][0] - m0);
            sfr[nt][1] = __expf(sfr[nt][1] - m0);
            sfr[nt][2] = __expf(sfr[nt][2] - m1);
            sfr[nt][3] = __expf(sfr[nt][3] - m1);
            s0 += sfr[nt][0] + sfr[nt][1];
            s1 += sfr[nt][2] + sfr[nt][3];
        }
        s0 += __shfl_xor_sync(0xffffffffu, s0, 1);
        s0 += __shfl_xor_sync(0xffffffffu, s0, 2);
        s1 += __shfl_xor_sync(0xffffffffu, s1, 1);
        s1 += __shfl_xor_sync(0xffffffffu, s1, 2);
        l0 = l0 * c0 + s0;
        l1 = l1 * c1 + s1;

#pragma unroll
        for (int nt = 0; nt < 16; ++nt) {
            o[nt][0] *= c0; o[nt][1] *= c0;
            o[nt][2] *= c1; o[nt][3] *= c1;
        }

        // ---- O += P @ V : FA2 identity — P A-frags come straight from sfr.
        // A-frag for k16-step ks (P cols 16ks..16ks+15):
        //   a0 = (row grp,   cols 16ks+2kq..+1) = pack2(sfr[2ks][0],   sfr[2ks][1])
        //   a1 = (row grp+8, same)              = pack2(sfr[2ks][2],   sfr[2ks][3])
        //   a2 = (row grp,   cols 16ks+8+2kq)   = pack2(sfr[2ks+1][0], sfr[2ks+1][1])
        //   a3 = (row grp+8, same)              = pack2(sfr[2ks+1][2], sfr[2ks+1][3])
#pragma unroll
        for (int ks = 0; ks < 4; ++ks) {
            uint32_t a[4];
            a[0] = pack2(sfr[2 * ks + 0][0], sfr[2 * ks + 0][1]);
            a[1] = pack2(sfr[2 * ks + 0][2], sfr[2 * ks + 0][3]);
            a[2] = pack2(sfr[2 * ks + 1][0], sfr[2 * ks + 1][1]);
            a[3] = pack2(sfr[2 * ks + 1][2], sfr[2 * ks + 1][3]);
            const uint32_t vbase = Vst + ((ks * 16 + lrow) * VST2 + lcol) * 2;
#pragma unroll
            for (int ntp = 0; ntp < 8; ++ntp) {
                uint32_t bb[4];
                LDSM4T(bb, vbase + ntp * 32);
                mma16(o[2 * ntp + 0], a, &bb[0]);
                mma16(o[2 * ntp + 1], a, &bb[2]);
            }
        }
    }

    // ---- epilogue: normalize, write fp32 [B,S,D] ----
    const int b = bh >> 3, h = bh & 7;
    float i0 = 1.0f / l0, i1 = 1.0f / l1;
    int q0 = qt * 64 + rowlo;
    float* r0 = O + ((size_t)b * S_LEN + q0) * DM + h * DKH;
    float* r1 = O + ((size_t)b * S_LEN + q0 + 8) * DM + h * DKH;
#pragma unroll
    for (int nt = 0; nt < 16; ++nt) {
        int col = nt * 8 + 2 * kq;
        *reinterpret_cast<float2*>(r0 + col) = make_float2(o[nt][0] * i0, o[nt][1] * i0);
        *reinterpret_cast<float2*>(r1 + col) = make_float2(o[nt][2] * i1, o[nt][3] * i1);
    }
}

// ---------------------------------------------------------------------------
// Residual + LayerNorm
// ---------------------------------------------------------------------------
__global__ __launch_bounds__(256)
void ln_kernel(const float* __restrict__ Oin, const float* __restrict__ X,
               const float* __restrict__ gamma, const float* __restrict__ beta,
               float* __restrict__ out)
{
    const int r = blockIdx.x;
    const int t = threadIdx.x;

    float4 o = reinterpret_cast<const float4*>(Oin + (size_t)r * DM)[t];
    float4 x = reinterpret_cast<const float4*>(X + (size_t)r * DM)[t];
    float v0 = o.x + x.x, v1 = o.y + x.y, v2 = o.z + x.z, v3 = o.w + x.w;

    float s1 = v0 + v1 + v2 + v3;
    float s2 = v0 * v0 + v1 * v1 + v2 * v2 + v3 * v3;
#pragma unroll
    for (int off = 16; off > 0; off >>= 1) {
        s1 += __shfl_xor_sync(0xffffffffu, s1, off);
        s2 += __shfl_xor_sync(0xffffffffu, s2, off);
    }

    __shared__ float rs1[8], rs2[8], stats[2];
    int warp = t >> 5, lane = t & 31;
    if (lane == 0) { rs1[warp] = s1; rs2[warp] = s2; }
    __syncthreads();
    if (t == 0) {
        float a = 0.0f, b2 = 0.0f;
#pragma unroll
        for (int wdx = 0; wdx < 8; ++wdx) { a += rs1[wdx]; b2 += rs2[wdx]; }
        float mean = a * (1.0f / 1024.0f);
        float var  = b2 * (1.0f / 1024.0f) - mean * mean;
        stats[0] = mean;
        stats[1] = rsqrtf(var + 1e-6f);
    }
    __syncthreads();
    float mean = stats[0], rstd = stats[1];

    float4 g  = reinterpret_cast<const float4*>(gamma)[t];
    float4 bb = reinterpret_cast<const float4*>(beta)[t];
    float4 y;
    y.x = (v0 - mean) * rstd * g.x + bb.x;
    y.y = (v1 - mean) * rstd * g.y + bb.y;
    y.z = (v2 - mean) * rstd * g.z + bb.z;
    y.w = (v3 - mean) * rstd * g.w + bb.w;
    reinterpret_cast<float4*>(out + (size_t)r * DM)[t] = y;
}

// ---------------------------------------------------------------------------
// Launcher
// ---------------------------------------------------------------------------
extern "C" void kernel_launch(void* const* d_in, const int* in_sizes, int n_in,
                              void* d_out, int out_size)
{
    const float* q     = (const float*)d_in[0];
    const float* k     = (const float*)d_in[1];
    const float* v     = (const float*)d_in[2];
    const float* Wq    = (const float*)d_in[3];
    const float* bq    = (const float*)d_in[4];
    const float* Wk    = (const float*)d_in[5];
    const float* bk    = (const float*)d_in[6];
    const float* Wv    = (const float*)d_in[7];
    const float* bv    = (const float*)d_in[8];
    const float* gamma = (const float*)d_in[9];
    const float* beta  = (const float*)d_in[10];
    float* out = (float*)d_out;

    __half *Qp, *Kp, *Vp, *WqT, *WkT, *WvT, *qh, *kh, *vh;
    float *Op;
    cudaGetSymbolAddress((void**)&Qp, g_Q);
    cudaGetSymbolAddress((void**)&Kp, g_K);
    cudaGetSymbolAddress((void**)&Vp, g_V);
    cudaGetSymbolAddress((void**)&Op, g_O);
    cudaGetSymbolAddress((void**)&WqT, g_WqT);
    cudaGetSymbolAddress((void**)&WkT, g_WkT);
    cudaGetSymbolAddress((void**)&WvT, g_WvT);
    cudaGetSymbolAddress((void**)&qh, g_qh);
    cudaGetSymbolAddress((void**)&kh, g_kh);
    cudaGetSymbolAddress((void**)&vh, g_vh);

    cudaFuncSetAttribute(gemm_h3, cudaFuncAttributeMaxDynamicSharedMemorySize,
                         GEMM_SMEM);
    cudaFuncSetAttribute(attn_h, cudaFuncAttributeMaxDynamicSharedMemorySize,
                         ATT_SMEM);

    // launch 0: all preprocessing (f2h x3 + weight transpose x3)
    prep<<<dim3(8192, 1, 6), 256>>>((const float4*)q, (const float4*)k,
                                    (const float4*)v, (uint2*)qh, (uint2*)kh,
                                    (uint2*)vh, Wq, Wk, Wv, WqT, WkT, WvT);

    // launch 1: fused QKV projections
    gemm_h3<<<dim3(8, 64, 3), 256, GEMM_SMEM>>>(qh, kh, vh, WqT, WkT, WvT,
                                                bq, bk, bv, Qp, Kp, Vp);

    // launch 2: attention (BQ=64, 3 CTAs/SM, P-in-register)
    attn_h<<<dim3(32, 32), 128, ATT_SMEM>>>(Qp, Kp, Vp, Op);

    // launch 3: residual + layernorm
    ln_kernel<<<8192, 256>>>(Op, q, gamma, beta, out);
}

// round 16
// speedup vs baseline: 1.2388x; 1.0964x over previous
#include <cuda_runtime.h>
#include <cuda_fp16.h>
#include <cstdint>

#define S_LEN 2048
#define B_SZ  4
#define H_NUM 8
#define DKH   128
#define DM    1024

// Scratch (device globals — no allocations allowed)
__device__ __half g_Q[(size_t)B_SZ * H_NUM * S_LEN * DKH];  // [B,H,S,dk] fp16
__device__ __half g_K[(size_t)B_SZ * H_NUM * S_LEN * DKH];
__device__ __half g_V[(size_t)B_SZ * H_NUM * S_LEN * DKH];
__device__ __half g_O[(size_t)B_SZ * S_LEN * DM];           // [B,S,D] fp16
__device__ __half g_WqT[DM * DM];                           // W^T fp16: [n][k]
__device__ __half g_WkT[DM * DM];
__device__ __half g_WvT[DM * DM];
__device__ __half g_qh[(size_t)B_SZ * S_LEN * DM];          // fp16 copies of inputs
__device__ __half g_kh[(size_t)B_SZ * S_LEN * DM];
__device__ __half g_vh[(size_t)B_SZ * S_LEN * DM];

// ---------------------------------------------------------------------------
// helpers
// ---------------------------------------------------------------------------
__device__ __forceinline__ uint32_t pack2(float lo, float hi) {
    __half2 h = __float22half2_rn(make_float2(lo, hi));
    return *reinterpret_cast<uint32_t*>(&h);
}
__device__ __forceinline__ uint32_t smem_addr(const void* p) {
    return (uint32_t)__cvta_generic_to_shared(p);
}
__device__ __forceinline__ void cpa16(uint32_t dst, const void* src) {
    asm volatile("cp.async.cg.shared.global [%0], [%1], 16;" :: "r"(dst), "l"(src));
}
#define CP_COMMIT() asm volatile("cp.async.commit_group;" ::: "memory")
#define CP_WAIT(n)  asm volatile("cp.async.wait_group %0;" :: "n"(n) : "memory")

// D += A*B, m16n8k16 fp16 in / fp32 accum
__device__ __forceinline__ void mma16(float* d, const uint32_t* a, const uint32_t* b) {
    asm volatile(
        "mma.sync.aligned.m16n8k16.row.col.f32.f16.f16.f32 "
        "{%0,%1,%2,%3},{%4,%5,%6,%7},{%8,%9},{%0,%1,%2,%3};"
        : "+f"(d[0]), "+f"(d[1]), "+f"(d[2]), "+f"(d[3])
        : "r"(a[0]), "r"(a[1]), "r"(a[2]), "r"(a[3]), "r"(b[0]), "r"(b[1]));
}
#define LDSM4(r, addr)                                                        \
    asm volatile("ldmatrix.sync.aligned.m8n8.x4.shared.b16 {%0,%1,%2,%3},[%4];" \
        : "=r"((r)[0]), "=r"((r)[1]), "=r"((r)[2]), "=r"((r)[3]) : "r"(addr))
#define LDSM4T(r, addr)                                                       \
    asm volatile("ldmatrix.sync.aligned.m8n8.x4.trans.shared.b16 {%0,%1,%2,%3},[%4];" \
        : "=r"((r)[0]), "=r"((r)[1]), "=r"((r)[2]), "=r"((r)[3]) : "r"(addr))

// ---------------------------------------------------------------------------
// Fused preprocessing (single launch):
//   z in 0..2 : fp32 -> fp16 convert of inputs q/k/v
//   z in 3..5 : fp32 -> fp16 transpose of weights Wq/Wk/Wv
// ---------------------------------------------------------------------------
__global__ __launch_bounds__(256)
void prep(const float4* __restrict__ q4, const float4* __restrict__ k4,
          const float4* __restrict__ v4, uint2* __restrict__ qh,
          uint2* __restrict__ kh, uint2* __restrict__ vh,
          const float* __restrict__ Wq, const float* __restrict__ Wk,
          const float* __restrict__ Wv, __half* __restrict__ WqT,
          __half* __restrict__ WkT, __half* __restrict__ WvT)
{
    const int z = blockIdx.z;
    if (z < 3) {
        const float4* in = (z == 0) ? q4 : (z == 1) ? k4 : v4;
        uint2*       out = (z == 0) ? qh : (z == 1) ? kh : vh;
        size_t i = (size_t)blockIdx.x * 256 + threadIdx.x;
        float4 v = in[i];
        uint2 u;
        u.x = pack2(v.x, v.y);
        u.y = pack2(v.z, v.w);
        out[i] = u;
    } else {
        if (blockIdx.x >= 1024) return;
        const float* in  = (z == 3) ? Wq : (z == 4) ? Wk : Wv;
        __half*      out = (z == 3) ? WqT : (z == 4) ? WkT : WvT;
        const int bx = blockIdx.x & 31, by = blockIdx.x >> 5;
        const int tx = threadIdx.x & 31, ty = threadIdx.x >> 5;

        __shared__ float t[32][33];
        int x  = bx * 32 + tx;
        int y0 = by * 32;
#pragma unroll
        for (int j = ty; j < 32; j += 8)
            t[j][tx] = in[(size_t)(y0 + j) * DM + x];
        __syncthreads();
        int x2 = by * 32 + tx;
#pragma unroll
        for (int j = ty; j < 32; j += 8)
            out[(size_t)(bx * 32 + j) * DM + x2] = __float2half(t[tx][j]);
    }
}

// ---------------------------------------------------------------------------
// Fused fp16 mma GEMM (3 projections via blockIdx.z), BK=64 per iteration,
// 3-stage cp.async pipeline, single barrier per iter. CTA 128x128, 8 warps.
// smem row stride 72 halves (144 B): ldmatrix phases conflict-free
// (bank = 4*row mod 32 within each 8-lane phase).
// ---------------------------------------------------------------------------
#define GROWB  144                        // bytes per smem row (64 halves + pad)
#define AMAT_B (128 * GROWB)              // 18432 bytes per matrix
#define STAGE_B (2 * AMAT_B)              // 36864 per stage
#define GEMM_SMEM (3 * STAGE_B)           // 110592 bytes

__global__ __launch_bounds__(256)
void gemm_h3(const __half* __restrict__ X0, const __half* __restrict__ X1,
             const __half* __restrict__ X2, const __half* __restrict__ W0,
             const __half* __restrict__ W1, const __half* __restrict__ W2,
             const float* __restrict__ b0, const float* __restrict__ b1,
             const float* __restrict__ b2, __half* __restrict__ o0,
             __half* __restrict__ o1, __half* __restrict__ o2)
{
    const int z = blockIdx.z;
    const __half* Xh   = (z == 0) ? X0 : (z == 1) ? X1 : X2;
    const __half* Wt   = (z == 0) ? W0 : (z == 1) ? W1 : W2;
    const float*  bias = (z == 0) ? b0 : (z == 1) ? b1 : b2;
    __half*       out  = (z == 0) ? o0 : (z == 1) ? o1 : o2;

    extern __shared__ __align__(16) char sm_raw[];
    const uint32_t sb = smem_addr(sm_raw);
    const int tid  = threadIdx.x;
    const int wid  = tid >> 5, lane = tid & 31;
    const int grp  = lane >> 2, kq = lane & 3;
    const int wm   = (wid >> 2) * 64, wn = (wid & 3) * 32;
    const int n0   = blockIdx.x * 128;   // h = blockIdx.x
    const int m0   = blockIdx.y * 128;

    float acc[4][4][4];
#pragma unroll
    for (int mt = 0; mt < 4; ++mt)
#pragma unroll
        for (int nt = 0; nt < 4; ++nt)
#pragma unroll
            for (int e = 0; e < 4; ++e) acc[mt][nt][e] = 0.0f;

    // cp.async tile loader: 1024 16B chunks per matrix (128 rows x 8), 4/thread
    auto load_stage = [&](int st, int kt) {
        const uint32_t base = sb + st * STAGE_B;
        const __half* Ag = Xh + (size_t)m0 * 1024 + kt * 64;
        const __half* Bg = Wt + (size_t)n0 * 1024 + kt * 64;
#pragma unroll
        for (int t = 0; t < 4; ++t) {
            int idx = tid + t * 256;          // 0..1023
            int r = idx >> 3, c = idx & 7;
            cpa16(base + r * GROWB + c * 16,          Ag + (size_t)r * 1024 + c * 8);
            cpa16(base + AMAT_B + r * GROWB + c * 16, Bg + (size_t)r * 1024 + c * 8);
        }
    };

    // ldmatrix per-lane addressing
    const int arow = wm + ((lane >> 3) & 1) * 8 + (lane & 7);
    const int acol = (lane >> 4) * 8;                  // halves
    const int brow = wn + ((lane >> 4) & 1) * 8 + (lane & 7);
    const int bcol = ((lane >> 3) & 1) * 8;

    load_stage(0, 0); CP_COMMIT();
    load_stage(1, 1); CP_COMMIT();

    for (int i = 0; i < 16; ++i) {
        CP_WAIT(1);
        __syncthreads();

        // refill stage freed last iteration
        if (i + 2 < 16) load_stage((i + 2) % 3, i + 2);
        CP_COMMIT();   // always commit to keep group accounting uniform

        const uint32_t Ac = sb + (i % 3) * STAGE_B;
        const uint32_t Bc = Ac + AMAT_B;
#pragma unroll
        for (int ks = 0; ks < 4; ++ks) {
            uint32_t a[4][4], b[2][4];
#pragma unroll
            for (int mt = 0; mt < 4; ++mt)
                LDSM4(a[mt], Ac + (arow + mt * 16) * GROWB + (ks * 16 + acol) * 2);
#pragma unroll
            for (int ntp = 0; ntp < 2; ++ntp)
                LDSM4(b[ntp], Bc + (brow + ntp * 16) * GROWB + (ks * 16 + bcol) * 2);
#pragma unroll
            for (int mt = 0; mt < 4; ++mt) {
                mma16(acc[mt][0], a[mt], &b[0][0]);
                mma16(acc[mt][1], a[mt], &b[0][2]);
                mma16(acc[mt][2], a[mt], &b[1][0]);
                mma16(acc[mt][3], a[mt], &b[1][2]);
            }
        }
    }

    // epilogue: bias + fp16 head-split store ([B,H,S,dk])
    const int h = blockIdx.x;
#pragma unroll
    for (int mt = 0; mt < 4; ++mt) {
#pragma unroll
        for (int half_ = 0; half_ < 2; ++half_) {
            int m = m0 + wm + mt * 16 + grp + half_ * 8;
            int b = m >> 11, s = m & 2047;
            __half* orow = out + (((size_t)b * H_NUM + h) * S_LEN + s) * DKH;
#pragma unroll
            for (int nt = 0; nt < 4; ++nt) {
                int nl = wn + nt * 8 + 2 * kq;
                float2 bv = *reinterpret_cast<const float2*>(bias + n0 + nl);
                uint32_t u = pack2(acc[mt][nt][half_ * 2 + 0] + bv.x,
                                   acc[mt][nt][half_ * 2 + 1] + bv.y);
                *reinterpret_cast<uint32_t*>(orow + nl) = u;
            }
        }
    }
}

// ---------------------------------------------------------------------------
// Flash attention, fp16 mma, BQ=64 (4 warps), BKV=64, dk=128.
// FA2 register identity (P never in smem), base-2 softmax, fp16 O output.
// 2-stage K/V cp.async pipeline, 3 CTAs/SM.
// ---------------------------------------------------------------------------
#define KST2 136
#define VST2 136
#define KV_K_B  (64 * KST2 * 2)              // 17408 bytes (K region)
#define KV_ST_B (2 * KV_K_B)                 // 34816 bytes per stage (K+V)
#define ATT_SMEM (2 * KV_ST_B)               // 69632 bytes

__global__ __launch_bounds__(128, 3)
void attn_h(const __half* __restrict__ Q, const __half* __restrict__ K,
            const __half* __restrict__ V, __half* __restrict__ O)
{
    extern __shared__ __align__(16) char sm_raw[];
    const uint32_t sb = smem_addr(sm_raw);

    const int qt  = (int)gridDim.x - 1 - (int)blockIdx.x;  // heavy tiles first
    const int bh  = blockIdx.y;
    const int tid = threadIdx.x;
    const int w   = tid >> 5, lane = tid & 31;
    const int grp = lane >> 2, kq = lane & 3;

    const __half* Qg = Q + ((size_t)bh * S_LEN + (size_t)qt * 64) * DKH;
    const __half* Kg = K + (size_t)bh * S_LEN * DKH;
    const __half* Vg = V + (size_t)bh * S_LEN * DKH;

    // kv tile loader into stage st (K + V), 1024 chunks over 128 threads
    auto load_kv = [&](int st, int kt) {
        const uint32_t kb = sb + st * KV_ST_B;
        const uint32_t vb = kb + KV_K_B;
        const __half* Kt = Kg + (size_t)kt * 64 * DKH;
        const __half* Vt = Vg + (size_t)kt * 64 * DKH;
#pragma unroll
        for (int j = 0; j < 8; ++j) {
            int idx = tid + j * 128;
            int r = idx >> 4, c = idx & 15;
            cpa16(kb + r * (KST2 * 2) + c * 16, Kt + (size_t)r * DKH + c * 8);
            cpa16(vb + r * (VST2 * 2) + c * 16, Vt + (size_t)r * DKH + c * 8);
        }
    };

    // ---- stage Q (64 rows x 16 chunks = 1024) into stage-1 K region ----
    {
        const uint32_t qb = sb + KV_ST_B;   // stage 1 K region
#pragma unroll
        for (int j = 0; j < 8; ++j) {
            int idx = tid + j * 128;
            int r = idx >> 4, c = idx & 15;
            cpa16(qb + r * (KST2 * 2) + c * 16, Qg + (size_t)r * DKH + c * 8);
        }
        CP_COMMIT();
        load_kv(0, 0);
        CP_COMMIT();
    }
    CP_WAIT(1);        // Q ready (kv0 may still be in flight)
    __syncthreads();

    // ---- extract Q A-fragments ----
    uint32_t qa[8][4];
    {
        const int qrow = w * 16 + ((lane >> 3) & 1) * 8 + (lane & 7);
        const int qcol = (lane >> 4) * 8;
        const uint32_t qb = sb + KV_ST_B;
#pragma unroll
        for (int ks = 0; ks < 8; ++ks)
            LDSM4(qa[ks], qb + (qrow * KST2 + ks * 16 + qcol) * 2);
    }

    float o[16][4];
#pragma unroll
    for (int nt = 0; nt < 16; ++nt)
#pragma unroll
        for (int e = 0; e < 4; ++e) o[nt][e] = 0.0f;
    float m0 = -1e30f, m1 = -1e30f, l0 = 0.0f, l1 = 0.0f;

    // base-2 softmax: fold log2(e) into the score scale
    const float sc2 = 0.12751669873124443f;  // (1/sqrt(128)) * log2(e)
    const int rowlo = w * 16 + grp;
    const int rowhi = rowlo + 8;

    // ldmatrix lane addressing (per iter)
    const int krow_l = ((lane >> 4) & 1) * 8 + (lane & 7);   // K B-frag rows
    const int kcol_l = ((lane >> 3) & 1) * 8;
    const int lrow   = ((lane >> 3) & 1) * 8 + (lane & 7);   // V trans rows
    const int lcol   = (lane >> 4) * 8;

    for (int kt = 0; kt <= qt; ++kt) {
        CP_WAIT(0);        // kv tile kt resident
        __syncthreads();   // all warps past last iter's compute + this wait

        // prefetch next kv tile into the other stage (overwrites oldest/Q)
        if (kt + 1 <= qt) load_kv((kt + 1) & 1, kt + 1);
        CP_COMMIT();       // always commit (uniform group accounting)

        const uint32_t Kst = sb + (kt & 1) * KV_ST_B;
        const uint32_t Vst = Kst + KV_K_B;

        // ---- S = Q @ K^T : 8 k16-steps x 4 nt-pairs (ldmatrix.x4) ----
        float sfr[8][4];
#pragma unroll
        for (int nt = 0; nt < 8; ++nt)
#pragma unroll
            for (int e = 0; e < 4; ++e) sfr[nt][e] = 0.0f;

#pragma unroll
        for (int ks = 0; ks < 8; ++ks) {
#pragma unroll
            for (int ntp = 0; ntp < 4; ++ntp) {
                uint32_t bb[4];
                LDSM4(bb, Kst + ((ntp * 16 + krow_l) * KST2 + ks * 16 + kcol_l) * 2);
                mma16(sfr[2 * ntp + 0], qa[ks], &bb[0]);
                mma16(sfr[2 * ntp + 1], qa[ks], &bb[2]);
            }
        }

        // scale (log2 domain) + causal mask on diagonal tile
#pragma unroll
        for (int nt = 0; nt < 8; ++nt) {
#pragma unroll
            for (int e = 0; e < 4; ++e) sfr[nt][e] *= sc2;
            if (kt == qt) {
                int col = nt * 8 + 2 * kq;
                if (col + 0 > rowlo) sfr[nt][0] = -1e9f;
                if (col + 1 > rowlo) sfr[nt][1] = -1e9f;
                if (col + 0 > rowhi) sfr[nt][2] = -1e9f;
                if (col + 1 > rowhi) sfr[nt][3] = -1e9f;
            }
        }

        // ---- online softmax (base-2) ----
        float mx0 = -1e30f, mx1 = -1e30f;
#pragma unroll
        for (int nt = 0; nt < 8; ++nt) {
            mx0 = fmaxf(mx0, fmaxf(sfr[nt][0], sfr[nt][1]));
            mx1 = fmaxf(mx1, fmaxf(sfr[nt][2], sfr[nt][3]));
        }
        mx0 = fmaxf(mx0, __shfl_xor_sync(0xffffffffu, mx0, 1));
        mx0 = fmaxf(mx0, __shfl_xor_sync(0xffffffffu, mx0, 2));
        mx1 = fmaxf(mx1, __shfl_xor_sync(0xffffffffu, mx1, 1));
        mx1 = fmaxf(mx1, __shfl_xor_sync(0xffffffffu, mx1, 2));

        float mn0 = fmaxf(m0, mx0), mn1 = fmaxf(m1, mx1);
        float c0 = exp2f(m0 - mn0), c1 = exp2f(m1 - mn1);
        m0 = mn0; m1 = mn1;

        float s0 = 0.0f, s1 = 0.0f;
#pragma unroll
        for (int nt = 0; nt < 8; ++nt) {
            sfr[nt][0] = exp2f(sfr[nt][0] - m0);
            sfr[nt][1] = exp2f(sfr[nt][1] - m0);
            sfr[nt][2] = exp2f(sfr[nt][2] - m1);
            sfr[nt][3] = exp2f(sfr[nt][3] - m1);
            s0 += sfr[nt][0] + sfr[nt][1];
            s1 += sfr[nt][2] + sfr[nt][3];
        }
        s0 += __shfl_xor_sync(0xffffffffu, s0, 1);
        s0 += __shfl_xor_sync(0xffffffffu, s0, 2);
        s1 += __shfl_xor_sync(0xffffffffu, s1, 1);
        s1 += __shfl_xor_sync(0xffffffffu, s1, 2);
        l0 = l0 * c0 + s0;
        l1 = l1 * c1 + s1;

#pragma unroll
        for (int nt = 0; nt < 16; ++nt) {
            o[nt][0] *= c0; o[nt][1] *= c0;
            o[nt][2] *= c1; o[nt][3] *= c1;
        }

        // ---- O += P @ V : FA2 identity — P A-frags come straight from sfr ----
#pragma unroll
        for (int ks = 0; ks < 4; ++ks) {
            uint32_t a[4];
            a[0] = pack2(sfr[2 * ks + 0][0], sfr[2 * ks + 0][1]);
            a[1] = pack2(sfr[2 * ks + 0][2], sfr[2 * ks + 0][3]);
            a[2] = pack2(sfr[2 * ks + 1][0], sfr[2 * ks + 1][1]);
            a[3] = pack2(sfr[2 * ks + 1][2], sfr[2 * ks + 1][3]);
            const uint32_t vbase = Vst + ((ks * 16 + lrow) * VST2 + lcol) * 2;
#pragma unroll
            for (int ntp = 0; ntp < 8; ++ntp) {
                uint32_t bb[4];
                LDSM4T(bb, vbase + ntp * 32);
                mma16(o[2 * ntp + 0], a, &bb[0]);
                mma16(o[2 * ntp + 1], a, &bb[2]);
            }
        }
    }

    // ---- epilogue: normalize, write fp16 [B,S,D] ----
    const int b = bh >> 3, h = bh & 7;
    float i0 = 1.0f / l0, i1 = 1.0f / l1;
    int q0 = qt * 64 + rowlo;
    __half* r0 = O + ((size_t)b * S_LEN + q0) * DM + h * DKH;
    __half* r1 = O + ((size_t)b * S_LEN + q0 + 8) * DM + h * DKH;
#pragma unroll
    for (int nt = 0; nt < 16; ++nt) {
        int col = nt * 8 + 2 * kq;
        *reinterpret_cast<uint32_t*>(r0 + col) = pack2(o[nt][0] * i0, o[nt][1] * i0);
        *reinterpret_cast<uint32_t*>(r1 + col) = pack2(o[nt][2] * i1, o[nt][3] * i1);
    }
}

// ---------------------------------------------------------------------------
// Residual + LayerNorm (fp16 attention output + fp32 residual input)
// ---------------------------------------------------------------------------
__global__ __launch_bounds__(256)
void ln_kernel(const __half* __restrict__ Oin, const float* __restrict__ X,
               const float* __restrict__ gamma, const float* __restrict__ beta,
               float* __restrict__ out)
{
    const int r = blockIdx.x;
    const int t = threadIdx.x;

    uint2 ou = reinterpret_cast<const uint2*>(Oin + (size_t)r * DM)[t];
    float2 f0 = __half22float2(*reinterpret_cast<__half2*>(&ou.x));
    float2 f1 = __half22float2(*reinterpret_cast<__half2*>(&ou.y));
    float4 x = reinterpret_cast<const float4*>(X + (size_t)r * DM)[t];
    float v0 = f0.x + x.x, v1 = f0.y + x.y, v2 = f1.x + x.z, v3 = f1.y + x.w;

    float s1 = v0 + v1 + v2 + v3;
    float s2 = v0 * v0 + v1 * v1 + v2 * v2 + v3 * v3;
#pragma unroll
    for (int off = 16; off > 0; off >>= 1) {
        s1 += __shfl_xor_sync(0xffffffffu, s1, off);
        s2 += __shfl_xor_sync(0xffffffffu, s2, off);
    }

    __shared__ float rs1[8], rs2[8], stats[2];
    int warp = t >> 5, lane = t & 31;
    if (lane == 0) { rs1[warp] = s1; rs2[warp] = s2; }
    __syncthreads();
    if (t == 0) {
        float a = 0.0f, b2 = 0.0f;
#pragma unroll
        for (int wdx = 0; wdx < 8; ++wdx) { a += rs1[wdx]; b2 += rs2[wdx]; }
        float mean = a * (1.0f / 1024.0f);
        float var  = b2 * (1.0f / 1024.0f) - mean * mean;
        stats[0] = mean;
        stats[1] = rsqrtf(var + 1e-6f);
    }
    __syncthreads();
    float mean = stats[0], rstd = stats[1];

    float4 g  = reinterpret_cast<const float4*>(gamma)[t];
    float4 bb = reinterpret_cast<const float4*>(beta)[t];
    float4 y;
    y.x = (v0 - mean) * rstd * g.x + bb.x;
    y.y = (v1 - mean) * rstd * g.y + bb.y;
    y.z = (v2 - mean) * rstd * g.z + bb.z;
    y.w = (v3 - mean) * rstd * g.w + bb.w;
    reinterpret_cast<float4*>(out + (size_t)r * DM)[t] = y;
}

// ---------------------------------------------------------------------------
// Launcher
// ---------------------------------------------------------------------------
extern "C" void kernel_launch(void* const* d_in, const int* in_sizes, int n_in,
                              void* d_out, int out_size)
{
    const float* q     = (const float*)d_in[0];
    const float* k     = (const float*)d_in[1];
    const float* v     = (const float*)d_in[2];
    const float* Wq    = (const float*)d_in[3];
    const float* bq    = (const float*)d_in[4];
    const float* Wk    = (const float*)d_in[5];
    const float* bk    = (const float*)d_in[6];
    const float* Wv    = (const float*)d_in[7];
    const float* bv    = (const float*)d_in[8];
    const float* gamma = (const float*)d_in[9];
    const float* beta  = (const float*)d_in[10];
    float* out = (float*)d_out;

    __half *Qp, *Kp, *Vp, *WqT, *WkT, *WvT, *qh, *kh, *vh, *Op;
    cudaGetSymbolAddress((void**)&Qp, g_Q);
    cudaGetSymbolAddress((void**)&Kp, g_K);
    cudaGetSymbolAddress((void**)&Vp, g_V);
    cudaGetSymbolAddress((void**)&Op, g_O);
    cudaGetSymbolAddress((void**)&WqT, g_WqT);
    cudaGetSymbolAddress((void**)&WkT, g_WkT);
    cudaGetSymbolAddress((void**)&WvT, g_WvT);
    cudaGetSymbolAddress((void**)&qh, g_qh);
    cudaGetSymbolAddress((void**)&kh, g_kh);
    cudaGetSymbolAddress((void**)&vh, g_vh);

    cudaFuncSetAttribute(gemm_h3, cudaFuncAttributeMaxDynamicSharedMemorySize,
                         GEMM_SMEM);
    cudaFuncSetAttribute(attn_h, cudaFuncAttributeMaxDynamicSharedMemorySize,
                         ATT_SMEM);

    // launch 0: all preprocessing (f2h x3 + weight transpose x3)
    prep<<<dim3(8192, 1, 6), 256>>>((const float4*)q, (const float4*)k,
                                    (const float4*)v, (uint2*)qh, (uint2*)kh,
                                    (uint2*)vh, Wq, Wk, Wv, WqT, WkT, WvT);

    // launch 1: fused QKV projections (BK=64, 3-stage pipeline)
    gemm_h3<<<dim3(8, 64, 3), 256, GEMM_SMEM>>>(qh, kh, vh, WqT, WkT, WvT,
                                                bq, bk, bv, Qp, Kp, Vp);

    // launch 2: attention (BQ=64, 3 CTAs/SM, P-in-register, fp16 O)
    attn_h<<<dim3(32, 32), 128, ATT_SMEM>>>(Qp, Kp, Vp, Op);

    // launch 3: residual + layernorm
    ln_kernel<<<8192, 256>>>(Op, q, gamma, beta, out);
}

// round 17
// speedup vs baseline: 1.2524x; 1.0110x over previous
#include <cuda_runtime.h>
#include <cuda_fp16.h>
#include <cstdint>

#define S_LEN 2048
#define B_SZ  4
#define H_NUM 8
#define DKH   128
#define DM    1024

// Scratch (device globals — no allocations allowed)
__device__ __half g_Q[(size_t)B_SZ * H_NUM * S_LEN * DKH];  // [B,H,S,dk] fp16
__device__ __half g_K[(size_t)B_SZ * H_NUM * S_LEN * DKH];
__device__ __half g_V[(size_t)B_SZ * H_NUM * S_LEN * DKH];
__device__ __half g_O[(size_t)B_SZ * S_LEN * DM];           // [B,S,D] fp16
__device__ __half g_WqT[DM * DM];                           // W^T fp16: [n][k]
__device__ __half g_WkT[DM * DM];
__device__ __half g_WvT[DM * DM];
__device__ __half g_qh[(size_t)B_SZ * S_LEN * DM];          // fp16 copies of inputs
__device__ __half g_kh[(size_t)B_SZ * S_LEN * DM];
__device__ __half g_vh[(size_t)B_SZ * S_LEN * DM];

// ---------------------------------------------------------------------------
// helpers
// ---------------------------------------------------------------------------
__device__ __forceinline__ uint32_t pack2(float lo, float hi) {
    __half2 h = __float22half2_rn(make_float2(lo, hi));
    return *reinterpret_cast<uint32_t*>(&h);
}
__device__ __forceinline__ uint32_t smem_addr(const void* p) {
    return (uint32_t)__cvta_generic_to_shared(p);
}
__device__ __forceinline__ void cpa16(uint32_t dst, const void* src) {
    asm volatile("cp.async.cg.shared.global [%0], [%1], 16;" :: "r"(dst), "l"(src));
}
#define CP_COMMIT() asm volatile("cp.async.commit_group;" ::: "memory")
#define CP_WAIT(n)  asm volatile("cp.async.wait_group %0;" :: "n"(n) : "memory")

// D += A*B, m16n8k16 fp16 in / fp32 accum
__device__ __forceinline__ void mma16(float* d, const uint32_t* a, const uint32_t* b) {
    asm volatile(
        "mma.sync.aligned.m16n8k16.row.col.f32.f16.f16.f32 "
        "{%0,%1,%2,%3},{%4,%5,%6,%7},{%8,%9},{%0,%1,%2,%3};"
        : "+f"(d[0]), "+f"(d[1]), "+f"(d[2]), "+f"(d[3])
        : "r"(a[0]), "r"(a[1]), "r"(a[2]), "r"(a[3]), "r"(b[0]), "r"(b[1]));
}
#define LDSM4(r, addr)                                                        \
    asm volatile("ldmatrix.sync.aligned.m8n8.x4.shared.b16 {%0,%1,%2,%3},[%4];" \
        : "=r"((r)[0]), "=r"((r)[1]), "=r"((r)[2]), "=r"((r)[3]) : "r"(addr))
#define LDSM4T(r, addr)                                                       \
    asm volatile("ldmatrix.sync.aligned.m8n8.x4.trans.shared.b16 {%0,%1,%2,%3},[%4];" \
        : "=r"((r)[0]), "=r"((r)[1]), "=r"((r)[2]), "=r"((r)[3]) : "r"(addr))

// ---------------------------------------------------------------------------
// Fused preprocessing (single launch):
//   z in 0..2 : fp32 -> fp16 convert of inputs q/k/v
//   z in 3..5 : fp32 -> fp16 transpose of weights Wq/Wk/Wv
// ---------------------------------------------------------------------------
__global__ __launch_bounds__(256)
void prep(const float4* __restrict__ q4, const float4* __restrict__ k4,
          const float4* __restrict__ v4, uint2* __restrict__ qh,
          uint2* __restrict__ kh, uint2* __restrict__ vh,
          const float* __restrict__ Wq, const float* __restrict__ Wk,
          const float* __restrict__ Wv, __half* __restrict__ WqT,
          __half* __restrict__ WkT, __half* __restrict__ WvT)
{
    const int z = blockIdx.z;
    if (z < 3) {
        const float4* in = (z == 0) ? q4 : (z == 1) ? k4 : v4;
        uint2*       out = (z == 0) ? qh : (z == 1) ? kh : vh;
        size_t i = (size_t)blockIdx.x * 256 + threadIdx.x;
        float4 v = in[i];
        uint2 u;
        u.x = pack2(v.x, v.y);
        u.y = pack2(v.z, v.w);
        out[i] = u;
    } else {
        if (blockIdx.x >= 1024) return;
        const float* in  = (z == 3) ? Wq : (z == 4) ? Wk : Wv;
        __half*      out = (z == 3) ? WqT : (z == 4) ? WkT : WvT;
        const int bx = blockIdx.x & 31, by = blockIdx.x >> 5;
        const int tx = threadIdx.x & 31, ty = threadIdx.x >> 5;

        __shared__ float t[32][33];
        int x  = bx * 32 + tx;
        int y0 = by * 32;
#pragma unroll
        for (int j = ty; j < 32; j += 8)
            t[j][tx] = in[(size_t)(y0 + j) * DM + x];
        __syncthreads();
        int x2 = by * 32 + tx;
#pragma unroll
        for (int j = ty; j < 32; j += 8)
            out[(size_t)(bx * 32 + j) * DM + x2] = __float2half(t[tx][j]);
    }
}

// ---------------------------------------------------------------------------
// PERSISTENT fused fp16 mma GEMM. 1536 tiles (3 mats x 8 n x 64 m) over a
// fixed grid of 296 CTAs (strided loop) — removes the partial-wave tail.
// BK=64/iter, 3-stage cp.async pipeline, CTA 128x128, 8 warps.
// smem row stride 72 halves (144 B): ldmatrix phases conflict-free.
// ---------------------------------------------------------------------------
#define GROWB  144                        // bytes per smem row (64 halves + pad)
#define AMAT_B (128 * GROWB)              // 18432 bytes per matrix
#define STAGE_B (2 * AMAT_B)              // 36864 per stage
#define GEMM_SMEM (3 * STAGE_B)           // 110592 bytes
#define GEMM_TILES 1536
#define GEMM_GRID  296

__global__ __launch_bounds__(256)
void gemm_h3(const __half* __restrict__ X0, const __half* __restrict__ X1,
             const __half* __restrict__ X2, const __half* __restrict__ W0,
             const __half* __restrict__ W1, const __half* __restrict__ W2,
             const float* __restrict__ b0, const float* __restrict__ b1,
             const float* __restrict__ b2, __half* __restrict__ o0,
             __half* __restrict__ o1, __half* __restrict__ o2)
{
    extern __shared__ __align__(16) char sm_raw[];
    const uint32_t sb = smem_addr(sm_raw);
    const int tid  = threadIdx.x;
    const int wid  = tid >> 5, lane = tid & 31;
    const int grp  = lane >> 2, kq = lane & 3;
    const int wm   = (wid >> 2) * 64, wn = (wid & 3) * 32;

    // ldmatrix per-lane addressing (tile-invariant)
    const int arow = wm + ((lane >> 3) & 1) * 8 + (lane & 7);
    const int acol = (lane >> 4) * 8;                  // halves
    const int brow = wn + ((lane >> 4) & 1) * 8 + (lane & 7);
    const int bcol = ((lane >> 3) & 1) * 8;

    for (int t = blockIdx.x; t < GEMM_TILES; t += GEMM_GRID) {
        const int z   = t >> 9;            // t / 512
        const int rem = t & 511;
        const int n0  = (rem & 7) * 128;   // h = rem & 7
        const int m0  = (rem >> 3) * 128;

        const __half* Xh   = (z == 0) ? X0 : (z == 1) ? X1 : X2;
        const __half* Wt   = (z == 0) ? W0 : (z == 1) ? W1 : W2;
        const float*  bias = (z == 0) ? b0 : (z == 1) ? b1 : b2;
        __half*       out  = (z == 0) ? o0 : (z == 1) ? o1 : o2;

        // stage-0 reuse hazard across tiles: iter 15 of the previous tile read
        // stage 0; make sure all warps are done before refilling it.
        __syncthreads();

        float acc[4][4][4];
#pragma unroll
        for (int mt = 0; mt < 4; ++mt)
#pragma unroll
            for (int nt = 0; nt < 4; ++nt)
#pragma unroll
                for (int e = 0; e < 4; ++e) acc[mt][nt][e] = 0.0f;

        // cp.async tile loader: 1024 16B chunks per matrix, 4/thread
        auto load_stage = [&](int st, int kt) {
            const uint32_t base = sb + st * STAGE_B;
            const __half* Ag = Xh + (size_t)m0 * 1024 + kt * 64;
            const __half* Bg = Wt + (size_t)n0 * 1024 + kt * 64;
#pragma unroll
            for (int u = 0; u < 4; ++u) {
                int idx = tid + u * 256;          // 0..1023
                int r = idx >> 3, c = idx & 7;
                cpa16(base + r * GROWB + c * 16,          Ag + (size_t)r * 1024 + c * 8);
                cpa16(base + AMAT_B + r * GROWB + c * 16, Bg + (size_t)r * 1024 + c * 8);
            }
        };

        load_stage(0, 0); CP_COMMIT();
        load_stage(1, 1); CP_COMMIT();

        for (int i = 0; i < 16; ++i) {
            CP_WAIT(1);
            __syncthreads();

            // refill stage freed last iteration
            if (i + 2 < 16) load_stage((i + 2) % 3, i + 2);
            CP_COMMIT();   // always commit to keep group accounting uniform

            const uint32_t Ac = sb + (i % 3) * STAGE_B;
            const uint32_t Bc = Ac + AMAT_B;
#pragma unroll
            for (int ks = 0; ks < 4; ++ks) {
                uint32_t a[4][4], b[2][4];
#pragma unroll
                for (int mt = 0; mt < 4; ++mt)
                    LDSM4(a[mt], Ac + (arow + mt * 16) * GROWB + (ks * 16 + acol) * 2);
#pragma unroll
                for (int ntp = 0; ntp < 2; ++ntp)
                    LDSM4(b[ntp], Bc + (brow + ntp * 16) * GROWB + (ks * 16 + bcol) * 2);
#pragma unroll
                for (int mt = 0; mt < 4; ++mt) {
                    mma16(acc[mt][0], a[mt], &b[0][0]);
                    mma16(acc[mt][1], a[mt], &b[0][2]);
                    mma16(acc[mt][2], a[mt], &b[1][0]);
                    mma16(acc[mt][3], a[mt], &b[1][2]);
                }
            }
        }

        // epilogue: bias + fp16 head-split store ([B,H,S,dk])
        const int h = rem & 7;
#pragma unroll
        for (int mt = 0; mt < 4; ++mt) {
#pragma unroll
            for (int half_ = 0; half_ < 2; ++half_) {
                int m = m0 + wm + mt * 16 + grp + half_ * 8;
                int b = m >> 11, s = m & 2047;
                __half* orow = out + (((size_t)b * H_NUM + h) * S_LEN + s) * DKH;
#pragma unroll
                for (int nt = 0; nt < 4; ++nt) {
                    int nl = wn + nt * 8 + 2 * kq;
                    float2 bv = *reinterpret_cast<const float2*>(bias + n0 + nl);
                    uint32_t u = pack2(acc[mt][nt][half_ * 2 + 0] + bv.x,
                                       acc[mt][nt][half_ * 2 + 1] + bv.y);
                    *reinterpret_cast<uint32_t*>(orow + nl) = u;
                }
            }
        }
    }
}

// ---------------------------------------------------------------------------
// Flash attention, fp16 mma, BQ=64 (4 warps), BKV=64, dk=128.
// FA2 register identity (P never in smem), base-2 softmax, fp16 O output,
// exact rescale-skip via ballot. 2-stage K/V cp.async pipeline, 3 CTAs/SM.
// ---------------------------------------------------------------------------
#define KST2 136
#define VST2 136
#define KV_K_B  (64 * KST2 * 2)              // 17408 bytes (K region)
#define KV_ST_B (2 * KV_K_B)                 // 34816 bytes per stage (K+V)
#define ATT_SMEM (2 * KV_ST_B)               // 69632 bytes

__global__ __launch_bounds__(128, 3)
void attn_h(const __half* __restrict__ Q, const __half* __restrict__ K,
            const __half* __restrict__ V, __half* __restrict__ O)
{
    extern __shared__ __align__(16) char sm_raw[];
    const uint32_t sb = smem_addr(sm_raw);

    const int qt  = (int)gridDim.x - 1 - (int)blockIdx.x;  // heavy tiles first
    const int bh  = blockIdx.y;
    const int tid = threadIdx.x;
    const int w   = tid >> 5, lane = tid & 31;
    const int grp = lane >> 2, kq = lane & 3;

    const __half* Qg = Q + ((size_t)bh * S_LEN + (size_t)qt * 64) * DKH;
    const __half* Kg = K + (size_t)bh * S_LEN * DKH;
    const __half* Vg = V + (size_t)bh * S_LEN * DKH;

    // kv tile loader into stage st (K + V), 1024 chunks over 128 threads
    auto load_kv = [&](int st, int kt) {
        const uint32_t kb = sb + st * KV_ST_B;
        const uint32_t vb = kb + KV_K_B;
        const __half* Kt = Kg + (size_t)kt * 64 * DKH;
        const __half* Vt = Vg + (size_t)kt * 64 * DKH;
#pragma unroll
        for (int j = 0; j < 8; ++j) {
            int idx = tid + j * 128;
            int r = idx >> 4, c = idx & 15;
            cpa16(kb + r * (KST2 * 2) + c * 16, Kt + (size_t)r * DKH + c * 8);
            cpa16(vb + r * (VST2 * 2) + c * 16, Vt + (size_t)r * DKH + c * 8);
        }
    };

    // ---- stage Q (64 rows x 16 chunks = 1024) into stage-1 K region ----
    {
        const uint32_t qb = sb + KV_ST_B;   // stage 1 K region
#pragma unroll
        for (int j = 0; j < 8; ++j) {
            int idx = tid + j * 128;
            int r = idx >> 4, c = idx & 15;
            cpa16(qb + r * (KST2 * 2) + c * 16, Qg + (size_t)r * DKH + c * 8);
        }
        CP_COMMIT();
        load_kv(0, 0);
        CP_COMMIT();
    }
    CP_WAIT(1);        // Q ready (kv0 may still be in flight)
    __syncthreads();

    // ---- extract Q A-fragments ----
    uint32_t qa[8][4];
    {
        const int qrow = w * 16 + ((lane >> 3) & 1) * 8 + (lane & 7);
        const int qcol = (lane >> 4) * 8;
        const uint32_t qb = sb + KV_ST_B;
#pragma unroll
        for (int ks = 0; ks < 8; ++ks)
            LDSM4(qa[ks], qb + (qrow * KST2 + ks * 16 + qcol) * 2);
    }

    float o[16][4];
#pragma unroll
    for (int nt = 0; nt < 16; ++nt)
#pragma unroll
        for (int e = 0; e < 4; ++e) o[nt][e] = 0.0f;
    float m0 = -1e30f, m1 = -1e30f, l0 = 0.0f, l1 = 0.0f;

    // base-2 softmax: fold log2(e) into the score scale
    const float sc2 = 0.12751669873124443f;  // (1/sqrt(128)) * log2(e)
    const int rowlo = w * 16 + grp;
    const int rowhi = rowlo + 8;

    // ldmatrix lane addressing (per iter)
    const int krow_l = ((lane >> 4) & 1) * 8 + (lane & 7);   // K B-frag rows
    const int kcol_l = ((lane >> 3) & 1) * 8;
    const int lrow   = ((lane >> 3) & 1) * 8 + (lane & 7);   // V trans rows
    const int lcol   = (lane >> 4) * 8;

    for (int kt = 0; kt <= qt; ++kt) {
        CP_WAIT(0);        // kv tile kt resident
        __syncthreads();   // all warps past last iter's compute + this wait

        // prefetch next kv tile into the other stage (overwrites oldest/Q)
        if (kt + 1 <= qt) load_kv((kt + 1) & 1, kt + 1);
        CP_COMMIT();       // always commit (uniform group accounting)

        const uint32_t Kst = sb + (kt & 1) * KV_ST_B;
        const uint32_t Vst = Kst + KV_K_B;

        // ---- S = Q @ K^T : 8 k16-steps x 4 nt-pairs (ldmatrix.x4) ----
        float sfr[8][4];
#pragma unroll
        for (int nt = 0; nt < 8; ++nt)
#pragma unroll
            for (int e = 0; e < 4; ++e) sfr[nt][e] = 0.0f;

#pragma unroll
        for (int ks = 0; ks < 8; ++ks) {
#pragma unroll
            for (int ntp = 0; ntp < 4; ++ntp) {
                uint32_t bb[4];
                LDSM4(bb, Kst + ((ntp * 16 + krow_l) * KST2 + ks * 16 + kcol_l) * 2);
                mma16(sfr[2 * ntp + 0], qa[ks], &bb[0]);
                mma16(sfr[2 * ntp + 1], qa[ks], &bb[2]);
            }
        }

        // scale (log2 domain) + causal mask on diagonal tile
#pragma unroll
        for (int nt = 0; nt < 8; ++nt) {
#pragma unroll
            for (int e = 0; e < 4; ++e) sfr[nt][e] *= sc2;
            if (kt == qt) {
                int col = nt * 8 + 2 * kq;
                if (col + 0 > rowlo) sfr[nt][0] = -1e9f;
                if (col + 1 > rowlo) sfr[nt][1] = -1e9f;
                if (col + 0 > rowhi) sfr[nt][2] = -1e9f;
                if (col + 1 > rowhi) sfr[nt][3] = -1e9f;
            }
        }

        // ---- online softmax (base-2) ----
        float mx0 = -1e30f, mx1 = -1e30f;
#pragma unroll
        for (int nt = 0; nt < 8; ++nt) {
            mx0 = fmaxf(mx0, fmaxf(sfr[nt][0], sfr[nt][1]));
            mx1 = fmaxf(mx1, fmaxf(sfr[nt][2], sfr[nt][3]));
        }
        mx0 = fmaxf(mx0, __shfl_xor_sync(0xffffffffu, mx0, 1));
        mx0 = fmaxf(mx0, __shfl_xor_sync(0xffffffffu, mx0, 2));
        mx1 = fmaxf(mx1, __shfl_xor_sync(0xffffffffu, mx1, 1));
        mx1 = fmaxf(mx1, __shfl_xor_sync(0xffffffffu, mx1, 2));

        float mn0 = fmaxf(m0, mx0), mn1 = fmaxf(m1, mx1);
        float c0 = exp2f(m0 - mn0), c1 = exp2f(m1 - mn1);
        m0 = mn0; m1 = mn1;

        float s0 = 0.0f, s1 = 0.0f;
#pragma unroll
        for (int nt = 0; nt < 8; ++nt) {
            sfr[nt][0] = exp2f(sfr[nt][0] - m0);
            sfr[nt][1] = exp2f(sfr[nt][1] - m0);
            sfr[nt][2] = exp2f(sfr[nt][2] - m1);
            sfr[nt][3] = exp2f(sfr[nt][3] - m1);
            s0 += sfr[nt][0] + sfr[nt][1];
            s1 += sfr[nt][2] + sfr[nt][3];
        }
        s0 += __shfl_xor_sync(0xffffffffu, s0, 1);
        s0 += __shfl_xor_sync(0xffffffffu, s0, 2);
        s1 += __shfl_xor_sync(0xffffffffu, s1, 1);
        s1 += __shfl_xor_sync(0xffffffffu, s1, 2);
        l0 = l0 * c0 + s0;
        l1 = l1 * c1 + s1;

        // rescale o only if any row's max changed (c==1.0 exactly otherwise;
        // skipping a multiply-by-one is exact, ballot keeps it warp-uniform)
        if (__ballot_sync(0xffffffffu, (c0 != 1.0f) || (c1 != 1.0f))) {
#pragma unroll
            for (int nt = 0; nt < 16; ++nt) {
                o[nt][0] *= c0; o[nt][1] *= c0;
                o[nt][2] *= c1; o[nt][3] *= c1;
            }
        }

        // ---- O += P @ V : FA2 identity — P A-frags come straight from sfr ----
#pragma unroll
        for (int ks = 0; ks < 4; ++ks) {
            uint32_t a[4];
            a[0] = pack2(sfr[2 * ks + 0][0], sfr[2 * ks + 0][1]);
            a[1] = pack2(sfr[2 * ks + 0][2], sfr[2 * ks + 0][3]);
            a[2] = pack2(sfr[2 * ks + 1][0], sfr[2 * ks + 1][1]);
            a[3] = pack2(sfr[2 * ks + 1][2], sfr[2 * ks + 1][3]);
            const uint32_t vbase = Vst + ((ks * 16 + lrow) * VST2 + lcol) * 2;
#pragma unroll
            for (int ntp = 0; ntp < 8; ++ntp) {
                uint32_t bb[4];
                LDSM4T(bb, vbase + ntp * 32);
                mma16(o[2 * ntp + 0], a, &bb[0]);
                mma16(o[2 * ntp + 1], a, &bb[2]);
            }
        }
    }

    // ---- epilogue: normalize, write fp16 [B,S,D] ----
    const int b = bh >> 3, h = bh & 7;
    float i0 = 1.0f / l0, i1 = 1.0f / l1;
    int q0 = qt * 64 + rowlo;
    __half* r0 = O + ((size_t)b * S_LEN + q0) * DM + h * DKH;
    __half* r1 = O + ((size_t)b * S_LEN + q0 + 8) * DM + h * DKH;
#pragma unroll
    for (int nt = 0; nt < 16; ++nt) {
        int col = nt * 8 + 2 * kq;
        *reinterpret_cast<uint32_t*>(r0 + col) = pack2(o[nt][0] * i0, o[nt][1] * i0);
        *reinterpret_cast<uint32_t*>(r1 + col) = pack2(o[nt][2] * i1, o[nt][3] * i1);
    }
}

// ---------------------------------------------------------------------------
// Residual + LayerNorm (fp16 attention output + fp32 residual input)
// ---------------------------------------------------------------------------
__global__ __launch_bounds__(256)
void ln_kernel(const __half* __restrict__ Oin, const float* __restrict__ X,
               const float* __restrict__ gamma, const float* __restrict__ beta,
               float* __restrict__ out)
{
    const int r = blockIdx.x;
    const int t = threadIdx.x;

    uint2 ou = reinterpret_cast<const uint2*>(Oin + (size_t)r * DM)[t];
    float2 f0 = __half22float2(*reinterpret_cast<__half2*>(&ou.x));
    float2 f1 = __half22float2(*reinterpret_cast<__half2*>(&ou.y));
    float4 x = reinterpret_cast<const float4*>(X + (size_t)r * DM)[t];
    float v0 = f0.x + x.x, v1 = f0.y + x.y, v2 = f1.x + x.z, v3 = f1.y + x.w;

    float s1 = v0 + v1 + v2 + v3;
    float s2 = v0 * v0 + v1 * v1 + v2 * v2 + v3 * v3;
#pragma unroll
    for (int off = 16; off > 0; off >>= 1) {
        s1 += __shfl_xor_sync(0xffffffffu, s1, off);
        s2 += __shfl_xor_sync(0xffffffffu, s2, off);
    }

    __shared__ float rs1[8], rs2[8], stats[2];
    int warp = t >> 5, lane = t & 31;
    if (lane == 0) { rs1[warp] = s1; rs2[warp] = s2; }
    __syncthreads();
    if (t == 0) {
        float a = 0.0f, b2 = 0.0f;
#pragma unroll
        for (int wdx = 0; wdx < 8; ++wdx) { a += rs1[wdx]; b2 += rs2[wdx]; }
        float mean = a * (1.0f / 1024.0f);
        float var  = b2 * (1.0f / 1024.0f) - mean * mean;
        stats[0] = mean;
        stats[1] = rsqrtf(var + 1e-6f);
    }
    __syncthreads();
    float mean = stats[0], rstd = stats[1];

    float4 g  = reinterpret_cast<const float4*>(gamma)[t];
    float4 bb = reinterpret_cast<const float4*>(beta)[t];
    float4 y;
    y.x = (v0 - mean) * rstd * g.x + bb.x;
    y.y = (v1 - mean) * rstd * g.y + bb.y;
    y.z = (v2 - mean) * rstd * g.z + bb.z;
    y.w = (v3 - mean) * rstd * g.w + bb.w;
    reinterpret_cast<float4*>(out + (size_t)r * DM)[t] = y;
}

// ---------------------------------------------------------------------------
// Launcher
// ---------------------------------------------------------------------------
extern "C" void kernel_launch(void* const* d_in, const int* in_sizes, int n_in,
                              void* d_out, int out_size)
{
    const float* q     = (const float*)d_in[0];
    const float* k     = (const float*)d_in[1];
    const float* v     = (const float*)d_in[2];
    const float* Wq    = (const float*)d_in[3];
    const float* bq    = (const float*)d_in[4];
    const float* Wk    = (const float*)d_in[5];
    const float* bk    = (const float*)d_in[6];
    const float* Wv    = (const float*)d_in[7];
    const float* bv    = (const float*)d_in[8];
    const float* gamma = (const float*)d_in[9];
    const float* beta  = (const float*)d_in[10];
    float* out = (float*)d_out;

    __half *Qp, *Kp, *Vp, *WqT, *WkT, *WvT, *qh, *kh, *vh, *Op;
    cudaGetSymbolAddress((void**)&Qp, g_Q);
    cudaGetSymbolAddress((void**)&Kp, g_K);
    cudaGetSymbolAddress((void**)&Vp, g_V);
    cudaGetSymbolAddress((void**)&Op, g_O);
    cudaGetSymbolAddress((void**)&WqT, g_WqT);
    cudaGetSymbolAddress((void**)&WkT, g_WkT);
    cudaGetSymbolAddress((void**)&WvT, g_WvT);
    cudaGetSymbolAddress((void**)&qh, g_qh);
    cudaGetSymbolAddress((void**)&kh, g_kh);
    cudaGetSymbolAddress((void**)&vh, g_vh);

    cudaFuncSetAttribute(gemm_h3, cudaFuncAttributeMaxDynamicSharedMemorySize,
                         GEMM_SMEM);
    cudaFuncSetAttribute(attn_h, cudaFuncAttributeMaxDynamicSharedMemorySize,
                         ATT_SMEM);

    // launch 0: all preprocessing (f2h x3 + weight transpose x3)
    prep<<<dim3(8192, 1, 6), 256>>>((const float4*)q, (const float4*)k,
                                    (const float4*)v, (uint2*)qh, (uint2*)kh,
                                    (uint2*)vh, Wq, Wk, Wv, WqT, WkT, WvT);

    // launch 1: fused QKV projections (persistent, BK=64, 3-stage pipeline)
    gemm_h3<<<GEMM_GRID, 256, GEMM_SMEM>>>(qh, kh, vh, WqT, WkT, WvT,
                                           bq, bk, bv, Qp, Kp, Vp);

    // launch 2: attention (BQ=64, 3 CTAs/SM, P-in-register, fp16 O)
    attn_h<<<dim3(32, 32), 128, ATT_SMEM>>>(Qp, Kp, Vp, Op);

    // launch 3: residual + layernorm
    ln_kernel<<<8192, 256>>>(Op, q, gamma, beta, out);
}